// round 5
// baseline (speedup 1.0000x reference)
#include <cuda_runtime.h>
#include <cuda_bf16.h>
#include <math.h>

#define NN   50000      // nodes
#define NE   600000     // edges
#define NEL  (NE + NN)  // edges + self loops
#define NG   100        // graphs
#define INC  128
#define HIDC 128
#define OUTC 64
#define DEMO 8

// ---------------- scratch (device globals; no allocation allowed) ----------------
__device__ float g_H[(size_t)NN * 128];   // GEMM output (pre-aggregation)
__device__ float g_A[(size_t)NN * 128];   // aggregated / layer input
__device__ int   g_deg[NN];
__device__ int   g_rowptr[NN + 1];
__device__ int   g_cursor[NN];
__device__ int   g_csrsrc[NEL];
__device__ float g_csrnorm[NEL];
__device__ float g_dinv[NN];
__device__ float g_pool[NG * OUTC];
__device__ float g_cnt[NG];

// ---------------- preprocessing ----------------
__global__ void k_deg_init() {
    int i = blockIdx.x * blockDim.x + threadIdx.x;
    if (i < NN) g_deg[i] = 1;   // self loop
}

__global__ void k_deg_count(const int* __restrict__ dst) {
    int e = blockIdx.x * blockDim.x + threadIdx.x;
    if (e < NE) atomicAdd(&g_deg[dst[e]], 1);
}

__global__ void k_dinv() {
    int i = blockIdx.x * blockDim.x + threadIdx.x;
    if (i < NN) g_dinv[i] = rsqrtf((float)g_deg[i]);
}

// single-block exclusive scan of g_deg -> g_rowptr (n = NN), shfl-based
__global__ void k_scan() {
    __shared__ int warp_sums[32];
    __shared__ int s_carry;
    int t = threadIdx.x;
    int lane = t & 31, w = t >> 5;
    if (t == 0) { g_rowptr[0] = 0; s_carry = 0; }
    __syncthreads();
    for (int base = 0; base < NN; base += 1024) {
        int idx = base + t;
        int v = (idx < NN) ? g_deg[idx] : 0;
        int x = v;
        #pragma unroll
        for (int o = 1; o < 32; o <<= 1) {
            int y = __shfl_up_sync(0xFFFFFFFFu, x, o);
            if (lane >= o) x += y;
        }
        if (lane == 31) warp_sums[w] = x;
        __syncthreads();
        if (w == 0) {
            int s = warp_sums[lane];
            #pragma unroll
            for (int o = 1; o < 32; o <<= 1) {
                int y = __shfl_up_sync(0xFFFFFFFFu, s, o);
                if (lane >= o) s += y;
            }
            warp_sums[lane] = s;
        }
        __syncthreads();
        int incl = x + (w > 0 ? warp_sums[w - 1] : 0) + s_carry;
        if (idx < NN) g_rowptr[idx + 1] = incl;
        __syncthreads();
        if (t == 1023) s_carry = incl;   // includes zero-padded tail -> total
        __syncthreads();
    }
}

__global__ void k_cursor() {
    int i = blockIdx.x * blockDim.x + threadIdx.x;
    if (i < NN) g_cursor[i] = g_rowptr[i];
}

__global__ void k_fill_csr(const int* __restrict__ src, const int* __restrict__ dst) {
    int i = blockIdx.x * blockDim.x + threadIdx.x;
    if (i >= NEL) return;
    int s, d;
    if (i < NE) { s = src[i]; d = dst[i]; }
    else        { s = d = i - NE; }          // self loop
    int pos = atomicAdd(&g_cursor[d], 1);
    g_csrsrc[pos]  = s;
    g_csrnorm[pos] = g_dinv[s] * g_dinv[d];
}

// ---------------- fp32 tiled GEMM:  C[M x N] = A[M x 128] @ W[128 x N] ----------------
// BM=64, BK=32, TM=4; threads = 256 laid out as 16x16. BN==N (128 or 64).
template <int BN, int TN>
__global__ __launch_bounds__(256)
void k_gemm(const float* __restrict__ A, const float* __restrict__ W,
            float* __restrict__ C, int M, int Ncols) {
    const int K = 128;
    __shared__ float Ast[32][68];   // [k][m], padded: 68*4 = 272 B (16B-aligned rows)
    __shared__ float Bs[32][BN];

    int tid = threadIdx.x;
    int tx = tid & 15;   // 16 col-groups of TN
    int ty = tid >> 4;   // 16 row-groups of 4
    int row0 = blockIdx.x * 64;

    float acc[4][TN];
    #pragma unroll
    for (int i = 0; i < 4; i++)
        #pragma unroll
        for (int j = 0; j < TN; j++) acc[i][j] = 0.f;

    for (int kt = 0; kt < K; kt += 32) {
        // A tile: 64 rows x 32 cols, stored transposed into Ast[k][m]
        #pragma unroll
        for (int i = tid; i < 512; i += 256) {
            int r = i >> 3, c4 = i & 7;
            float4 v = make_float4(0.f, 0.f, 0.f, 0.f);
            if (row0 + r < M)
                v = *(const float4*)&A[(size_t)(row0 + r) * K + kt + c4 * 4];
            Ast[c4 * 4 + 0][r] = v.x;
            Ast[c4 * 4 + 1][r] = v.y;
            Ast[c4 * 4 + 2][r] = v.z;
            Ast[c4 * 4 + 3][r] = v.w;
        }
        // B tile: 32 x BN
        #pragma unroll
        for (int i = tid; i < 32 * BN / 4; i += 256) {
            int r = i / (BN / 4), c4 = i % (BN / 4);
            float4 v = *(const float4*)&W[(size_t)(kt + r) * Ncols + c4 * 4];
            *(float4*)&Bs[r][c4 * 4] = v;
        }
        __syncthreads();

        #pragma unroll
        for (int k = 0; k < 32; k++) {
            float4 a = *(const float4*)&Ast[k][ty * 4];
            float av[4] = {a.x, a.y, a.z, a.w};
            float bv[TN];
            #pragma unroll
            for (int j4 = 0; j4 < TN / 4; j4++) {
                float4 b = *(const float4*)&Bs[k][tx * TN + j4 * 4];
                bv[j4 * 4 + 0] = b.x; bv[j4 * 4 + 1] = b.y;
                bv[j4 * 4 + 2] = b.z; bv[j4 * 4 + 3] = b.w;
            }
            #pragma unroll
            for (int i = 0; i < 4; i++)
                #pragma unroll
                for (int j = 0; j < TN; j++)
                    acc[i][j] += av[i] * bv[j];
        }
        __syncthreads();
    }

    #pragma unroll
    for (int i = 0; i < 4; i++) {
        int r = row0 + ty * 4 + i;
        if (r < M) {
            #pragma unroll
            for (int j = 0; j < TN; j++)
                C[(size_t)r * Ncols + tx * TN + j] = acc[i][j];
        }
    }
}

// ---------------- CSR gather-aggregation (no float atomics): out = relu(bias + sum norm*H[src]) ----
__global__ void k_agg(const float* __restrict__ H, const float* __restrict__ bias,
                      float* __restrict__ out, int C) {
    int node = blockIdx.x;
    int c = threadIdx.x;
    int beg = g_rowptr[node], end = g_rowptr[node + 1];
    float acc = bias[c];
    for (int e = beg; e < end; e++) {
        int s = g_csrsrc[e];
        float w = g_csrnorm[e];
        acc += w * H[(size_t)s * C + c];
    }
    out[(size_t)node * C + c] = fmaxf(acc, 0.f);
}

// ---------------- pooling ----------------
__global__ void k_pool_zero() {
    int i = blockIdx.x * blockDim.x + threadIdx.x;
    if (i < NG * OUTC) g_pool[i] = 0.f;
    if (i < NG) g_cnt[i] = 0.f;
}

__global__ void k_pool(const float* __restrict__ A, const int* __restrict__ batch) {
    int idx = blockIdx.x * blockDim.x + threadIdx.x;
    if (idx >= NN * OUTC) return;
    int node = idx >> 6;       // /64
    int c = idx & 63;
    int g = batch[node];
    atomicAdd(&g_pool[g * OUTC + c], A[idx]);
    if (c == 0) atomicAdd(&g_cnt[g], 1.f);
}

// ---------------- final MLP: (pooled | demo) @ Wf1 relu @ Wf2 relu @ Wf3 ----------------
__global__ void k_mlp(const float* __restrict__ demo,
                      const float* __restrict__ Wf1, const float* __restrict__ bf1,
                      const float* __restrict__ Wf2, const float* __restrict__ bf2,
                      const float* __restrict__ Wf3, const float* __restrict__ bf3,
                      float* __restrict__ out) {
    int g = blockIdx.x;
    int t = threadIdx.x;            // 64 threads
    __shared__ float z[72];
    __shared__ float z1[64];
    __shared__ float z2[32];

    float invc = 1.f / fmaxf(g_cnt[g], 1.f);
    if (t < 64) z[t] = g_pool[g * OUTC + t] * invc;
    if (t < DEMO) z[64 + t] = demo[g * DEMO + t];
    __syncthreads();

    {   // 72 -> 64
        float acc = bf1[t];
        #pragma unroll 8
        for (int k = 0; k < 72; k++) acc += z[k] * Wf1[k * 64 + t];
        z1[t] = fmaxf(acc, 0.f);
    }
    __syncthreads();
    if (t < 32) {   // 64 -> 32
        float acc = bf2[t];
        #pragma unroll 8
        for (int k = 0; k < 64; k++) acc += z1[k] * Wf2[k * 32 + t];
        z2[t] = fmaxf(acc, 0.f);
    }
    __syncthreads();
    if (t < 2) {    // 32 -> 2
        float acc = bf3[t];
        #pragma unroll
        for (int k = 0; k < 32; k++) acc += z2[k] * Wf3[k * 2 + t];
        out[g * 2 + t] = acc;
    }
}

// ---------------- launch ----------------
extern "C" void kernel_launch(void* const* d_in, const int* in_sizes, int n_in,
                              void* d_out, int out_size) {
    const float* x     = (const float*)d_in[0];
    const int*   ei    = (const int*)  d_in[1];   // [2, NE]: src row then dst row
    const int*   batch = (const int*)  d_in[2];
    const float* demo  = (const float*)d_in[3];
    const float* W1 = (const float*)d_in[4];  const float* b1 = (const float*)d_in[5];
    const float* W2 = (const float*)d_in[6];  const float* b2 = (const float*)d_in[7];
    const float* W3 = (const float*)d_in[8];  const float* b3 = (const float*)d_in[9];
    const float* Wf1 = (const float*)d_in[10]; const float* bf1 = (const float*)d_in[11];
    const float* Wf2 = (const float*)d_in[12]; const float* bf2 = (const float*)d_in[13];
    const float* Wf3 = (const float*)d_in[14]; const float* bf3 = (const float*)d_in[15];
    float* out = (float*)d_out;

    const int* src = ei;
    const int* dst = ei + NE;

    float *H, *A;
    cudaGetSymbolAddress((void**)&H, g_H);
    cudaGetSymbolAddress((void**)&A, g_A);

    const int T = 256;
    // --- graph preprocessing (recomputed every call; deterministic up to fp sum order) ---
    k_deg_init<<<(NN + T - 1) / T, T>>>();
    k_deg_count<<<(NE + T - 1) / T, T>>>(dst);
    k_dinv<<<(NN + T - 1) / T, T>>>();
    k_scan<<<1, 1024>>>();
    k_cursor<<<(NN + T - 1) / T, T>>>();
    k_fill_csr<<<(NEL + T - 1) / T, T>>>(src, dst);

    const int gemm_grid = (NN + 63) / 64;   // 782
    // --- layer 1 ---
    k_gemm<128, 8><<<gemm_grid, 256>>>(x, W1, H, NN, HIDC);
    k_agg<<<NN, 128>>>(H, b1, A, HIDC);
    // --- layer 2 ---
    k_gemm<128, 8><<<gemm_grid, 256>>>(A, W2, H, NN, HIDC);
    k_agg<<<NN, 128>>>(H, b2, A, HIDC);
    // --- layer 3 ---
    k_gemm<64, 4><<<gemm_grid, 256>>>(A, W3, H, NN, OUTC);
    k_agg<<<NN, 64>>>(H, b3, A, OUTC);

    // --- pooling + MLP head ---
    k_pool_zero<<<(NG * OUTC + T - 1) / T, T>>>();
    k_pool<<<(NN * OUTC + T - 1) / T, T>>>(A, batch);
    k_mlp<<<NG, 64>>>(demo, Wf1, bf1, Wf2, bf2, Wf3, bf3, out);
}

// round 6
// speedup vs baseline: 1.0001x; 1.0001x over previous
#include <cuda_runtime.h>
#include <cuda_bf16.h>
#include <math.h>

#define NN   50000      // nodes
#define NE   600000     // edges
#define NEL  (NE + NN)  // edges + self loops
#define NG   100        // graphs
#define INC  128
#define HIDC 128
#define OUTC 64
#define DEMO 8

// ---------------- scratch (device globals; no allocation allowed) ----------------
__device__ float g_H[(size_t)NN * 128];   // GEMM output (pre-aggregation)
__device__ float g_A[(size_t)NN * 128];   // aggregated / layer input
__device__ int   g_deg[NN];
__device__ int   g_rowptr[NN + 1];
__device__ int   g_cursor[NN];
__device__ int   g_csrsrc[NEL];
__device__ float g_csrnorm[NEL];
__device__ float g_dinv[NN];
__device__ float g_pool[NG * OUTC];
__device__ float g_cnt[NG];

// ---------------- preprocessing ----------------
__global__ void k_deg_init() {
    int i = blockIdx.x * blockDim.x + threadIdx.x;
    if (i < NN) g_deg[i] = 1;   // self loop
}

__global__ void k_deg_count(const int* __restrict__ dst) {
    int e = blockIdx.x * blockDim.x + threadIdx.x;
    if (e < NE) atomicAdd(&g_deg[dst[e]], 1);
}

__global__ void k_dinv() {
    int i = blockIdx.x * blockDim.x + threadIdx.x;
    if (i < NN) g_dinv[i] = rsqrtf((float)g_deg[i]);
}

// single-block exclusive scan of g_deg -> g_rowptr (n = NN), shfl-based
__global__ void k_scan() {
    __shared__ int warp_sums[32];
    __shared__ int s_carry;
    int t = threadIdx.x;
    int lane = t & 31, w = t >> 5;
    if (t == 0) { g_rowptr[0] = 0; s_carry = 0; }
    __syncthreads();
    for (int base = 0; base < NN; base += 1024) {
        int idx = base + t;
        int v = (idx < NN) ? g_deg[idx] : 0;
        int x = v;
        #pragma unroll
        for (int o = 1; o < 32; o <<= 1) {
            int y = __shfl_up_sync(0xFFFFFFFFu, x, o);
            if (lane >= o) x += y;
        }
        if (lane == 31) warp_sums[w] = x;
        __syncthreads();
        if (w == 0) {
            int s = warp_sums[lane];
            #pragma unroll
            for (int o = 1; o < 32; o <<= 1) {
                int y = __shfl_up_sync(0xFFFFFFFFu, s, o);
                if (lane >= o) s += y;
            }
            warp_sums[lane] = s;
        }
        __syncthreads();
        int incl = x + (w > 0 ? warp_sums[w - 1] : 0) + s_carry;
        if (idx < NN) g_rowptr[idx + 1] = incl;
        __syncthreads();
        if (t == 1023) s_carry = incl;   // includes zero-padded tail -> total
        __syncthreads();
    }
}

__global__ void k_cursor() {
    int i = blockIdx.x * blockDim.x + threadIdx.x;
    if (i < NN) g_cursor[i] = g_rowptr[i];
}

__global__ void k_fill_csr(const int* __restrict__ src, const int* __restrict__ dst) {
    int i = blockIdx.x * blockDim.x + threadIdx.x;
    if (i >= NEL) return;
    int s, d;
    if (i < NE) { s = src[i]; d = dst[i]; }
    else        { s = d = i - NE; }          // self loop
    int pos = atomicAdd(&g_cursor[d], 1);
    g_csrsrc[pos]  = s;
    g_csrnorm[pos] = g_dinv[s] * g_dinv[d];
}

// ---------------- fp32 tiled GEMM:  C[M x N] = A[M x 128] @ W[128 x N] ----------------
// BM=64, BK=32, TM=4; threads = 256 laid out as 16x16. BN==N (128 or 64).
template <int BN, int TN>
__global__ __launch_bounds__(256)
void k_gemm(const float* __restrict__ A, const float* __restrict__ W,
            float* __restrict__ C, int M, int Ncols) {
    const int K = 128;
    __shared__ float Ast[32][68];   // [k][m], padded: 68*4 = 272 B (16B-aligned rows)
    __shared__ float Bs[32][BN];

    int tid = threadIdx.x;
    int tx = tid & 15;   // 16 col-groups of TN
    int ty = tid >> 4;   // 16 row-groups of 4
    int row0 = blockIdx.x * 64;

    float acc[4][TN];
    #pragma unroll
    for (int i = 0; i < 4; i++)
        #pragma unroll
        for (int j = 0; j < TN; j++) acc[i][j] = 0.f;

    for (int kt = 0; kt < K; kt += 32) {
        // A tile: 64 rows x 32 cols, stored transposed into Ast[k][m]
        #pragma unroll
        for (int i = tid; i < 512; i += 256) {
            int r = i >> 3, c4 = i & 7;
            float4 v = make_float4(0.f, 0.f, 0.f, 0.f);
            if (row0 + r < M)
                v = *(const float4*)&A[(size_t)(row0 + r) * K + kt + c4 * 4];
            Ast[c4 * 4 + 0][r] = v.x;
            Ast[c4 * 4 + 1][r] = v.y;
            Ast[c4 * 4 + 2][r] = v.z;
            Ast[c4 * 4 + 3][r] = v.w;
        }
        // B tile: 32 x BN
        #pragma unroll
        for (int i = tid; i < 32 * BN / 4; i += 256) {
            int r = i / (BN / 4), c4 = i % (BN / 4);
            float4 v = *(const float4*)&W[(size_t)(kt + r) * Ncols + c4 * 4];
            *(float4*)&Bs[r][c4 * 4] = v;
        }
        __syncthreads();

        #pragma unroll
        for (int k = 0; k < 32; k++) {
            float4 a = *(const float4*)&Ast[k][ty * 4];
            float av[4] = {a.x, a.y, a.z, a.w};
            float bv[TN];
            #pragma unroll
            for (int j4 = 0; j4 < TN / 4; j4++) {
                float4 b = *(const float4*)&Bs[k][tx * TN + j4 * 4];
                bv[j4 * 4 + 0] = b.x; bv[j4 * 4 + 1] = b.y;
                bv[j4 * 4 + 2] = b.z; bv[j4 * 4 + 3] = b.w;
            }
            #pragma unroll
            for (int i = 0; i < 4; i++)
                #pragma unroll
                for (int j = 0; j < TN; j++)
                    acc[i][j] += av[i] * bv[j];
        }
        __syncthreads();
    }

    #pragma unroll
    for (int i = 0; i < 4; i++) {
        int r = row0 + ty * 4 + i;
        if (r < M) {
            #pragma unroll
            for (int j = 0; j < TN; j++)
                C[(size_t)r * Ncols + tx * TN + j] = acc[i][j];
        }
    }
}

// ---------------- CSR gather-aggregation (no float atomics): out = relu(bias + sum norm*H[src]) ----
__global__ void k_agg(const float* __restrict__ H, const float* __restrict__ bias,
                      float* __restrict__ out, int C) {
    int node = blockIdx.x;
    int c = threadIdx.x;
    int beg = g_rowptr[node], end = g_rowptr[node + 1];
    float acc = bias[c];
    for (int e = beg; e < end; e++) {
        int s = g_csrsrc[e];
        float w = g_csrnorm[e];
        acc += w * H[(size_t)s * C + c];
    }
    out[(size_t)node * C + c] = fmaxf(acc, 0.f);
}

// ---------------- pooling ----------------
__global__ void k_pool_zero() {
    int i = blockIdx.x * blockDim.x + threadIdx.x;
    if (i < NG * OUTC) g_pool[i] = 0.f;
    if (i < NG) g_cnt[i] = 0.f;
}

__global__ void k_pool(const float* __restrict__ A, const int* __restrict__ batch) {
    int idx = blockIdx.x * blockDim.x + threadIdx.x;
    if (idx >= NN * OUTC) return;
    int node = idx >> 6;       // /64
    int c = idx & 63;
    int g = batch[node];
    atomicAdd(&g_pool[g * OUTC + c], A[idx]);
    if (c == 0) atomicAdd(&g_cnt[g], 1.f);
}

// ---------------- final MLP: (pooled | demo) @ Wf1 relu @ Wf2 relu @ Wf3 ----------------
__global__ void k_mlp(const float* __restrict__ demo,
                      const float* __restrict__ Wf1, const float* __restrict__ bf1,
                      const float* __restrict__ Wf2, const float* __restrict__ bf2,
                      const float* __restrict__ Wf3, const float* __restrict__ bf3,
                      float* __restrict__ out) {
    int g = blockIdx.x;
    int t = threadIdx.x;            // 64 threads
    __shared__ float z[72];
    __shared__ float z1[64];
    __shared__ float z2[32];

    float invc = 1.f / fmaxf(g_cnt[g], 1.f);
    if (t < 64) z[t] = g_pool[g * OUTC + t] * invc;
    if (t < DEMO) z[64 + t] = demo[g * DEMO + t];
    __syncthreads();

    {   // 72 -> 64
        float acc = bf1[t];
        #pragma unroll 8
        for (int k = 0; k < 72; k++) acc += z[k] * Wf1[k * 64 + t];
        z1[t] = fmaxf(acc, 0.f);
    }
    __syncthreads();
    if (t < 32) {   // 64 -> 32
        float acc = bf2[t];
        #pragma unroll 8
        for (int k = 0; k < 64; k++) acc += z1[k] * Wf2[k * 32 + t];
        z2[t] = fmaxf(acc, 0.f);
    }
    __syncthreads();
    if (t < 2) {    // 32 -> 2
        float acc = bf3[t];
        #pragma unroll
        for (int k = 0; k < 32; k++) acc += z2[k] * Wf3[k * 2 + t];
        out[g * 2 + t] = acc;
    }
}

// ---------------- launch ----------------
extern "C" void kernel_launch(void* const* d_in, const int* in_sizes, int n_in,
                              void* d_out, int out_size) {
    const float* x     = (const float*)d_in[0];
    const int*   ei    = (const int*)  d_in[1];   // [2, NE]: src row then dst row
    const int*   batch = (const int*)  d_in[2];
    const float* demo  = (const float*)d_in[3];
    const float* W1 = (const float*)d_in[4];  const float* b1 = (const float*)d_in[5];
    const float* W2 = (const float*)d_in[6];  const float* b2 = (const float*)d_in[7];
    const float* W3 = (const float*)d_in[8];  const float* b3 = (const float*)d_in[9];
    const float* Wf1 = (const float*)d_in[10]; const float* bf1 = (const float*)d_in[11];
    const float* Wf2 = (const float*)d_in[12]; const float* bf2 = (const float*)d_in[13];
    const float* Wf3 = (const float*)d_in[14]; const float* bf3 = (const float*)d_in[15];
    float* out = (float*)d_out;

    const int* src = ei;
    const int* dst = ei + NE;

    float *H, *A;
    cudaGetSymbolAddress((void**)&H, g_H);
    cudaGetSymbolAddress((void**)&A, g_A);

    const int T = 256;
    // --- graph preprocessing (recomputed every call; deterministic up to fp sum order) ---
    k_deg_init<<<(NN + T - 1) / T, T>>>();
    k_deg_count<<<(NE + T - 1) / T, T>>>(dst);
    k_dinv<<<(NN + T - 1) / T, T>>>();
    k_scan<<<1, 1024>>>();
    k_cursor<<<(NN + T - 1) / T, T>>>();
    k_fill_csr<<<(NEL + T - 1) / T, T>>>(src, dst);

    const int gemm_grid = (NN + 63) / 64;   // 782
    // --- layer 1 ---
    k_gemm<128, 8><<<gemm_grid, 256>>>(x, W1, H, NN, HIDC);
    k_agg<<<NN, 128>>>(H, b1, A, HIDC);
    // --- layer 2 ---
    k_gemm<128, 8><<<gemm_grid, 256>>>(A, W2, H, NN, HIDC);
    k_agg<<<NN, 128>>>(H, b2, A, HIDC);
    // --- layer 3 ---
    k_gemm<64, 4><<<gemm_grid, 256>>>(A, W3, H, NN, OUTC);
    k_agg<<<NN, 64>>>(H, b3, A, OUTC);

    // --- pooling + MLP head ---
    k_pool_zero<<<(NG * OUTC + T - 1) / T, T>>>();
    k_pool<<<(NN * OUTC + T - 1) / T, T>>>(A, batch);
    k_mlp<<<NG, 64>>>(demo, Wf1, bf1, Wf2, bf2, Wf3, bf3, out);
}

// round 7
// speedup vs baseline: 1.3829x; 1.3828x over previous
#include <cuda_runtime.h>
#include <cuda_bf16.h>
#include <math.h>

#define NN   50000      // nodes
#define NE   600000     // edges
#define NEL  (NE + NN)  // edges + self loops
#define NG   100        // graphs
#define INC  128
#define HIDC 128
#define OUTC 64
#define DEMO 8

#define SCAN_BLK  1024
#define SCAN_NBLK ((NN + SCAN_BLK - 1) / SCAN_BLK)   // 49

// ---------------- scratch (device globals; no allocation allowed) ----------------
__device__ float g_H[(size_t)NN * 128];   // GEMM output (pre-aggregation)
__device__ float g_A[(size_t)NN * 128];   // aggregated / layer input
__device__ int   g_deg[NN];
__device__ int   g_rowptr[NN + 1];
__device__ int   g_cursor[NN];
__device__ int   g_csrsrc[NEL];
__device__ float g_csrnorm[NEL];
__device__ float g_dinv[NN];
__device__ int   g_bsum[SCAN_NBLK];
__device__ int   g_boff[SCAN_NBLK];

// ---------------- preprocessing ----------------
__global__ void k_deg_init() {
    int i = blockIdx.x * blockDim.x + threadIdx.x;
    if (i < NN) g_deg[i] = 1;   // self loop
}

__global__ void k_deg_count(const int* __restrict__ dst) {
    int e = blockIdx.x * blockDim.x + threadIdx.x;
    if (e < NE) atomicAdd(&g_deg[dst[e]], 1);
}

// phase 1: per-block inclusive scan of g_deg -> rowptr[i+1] (block-local),
// block totals -> g_bsum. Also computes dinv (fused).
__global__ void k_scan1() {
    __shared__ int wsum[32];
    int t = threadIdx.x, lane = t & 31, w = t >> 5;
    int idx = blockIdx.x * SCAN_BLK + t;
    int v = 0;
    if (idx < NN) {
        v = g_deg[idx];
        g_dinv[idx] = rsqrtf((float)v);
    }
    int x = v;
    #pragma unroll
    for (int o = 1; o < 32; o <<= 1) {
        int y = __shfl_up_sync(0xFFFFFFFFu, x, o);
        if (lane >= o) x += y;
    }
    if (lane == 31) wsum[w] = x;
    __syncthreads();
    if (w == 0) {
        int s = wsum[lane];
        #pragma unroll
        for (int o = 1; o < 32; o <<= 1) {
            int y = __shfl_up_sync(0xFFFFFFFFu, s, o);
            if (lane >= o) s += y;
        }
        wsum[lane] = s;
    }
    __syncthreads();
    int incl = x + (w > 0 ? wsum[w - 1] : 0);
    if (idx < NN) g_rowptr[idx + 1] = incl;             // block-local inclusive
    if (t == SCAN_BLK - 1) g_bsum[blockIdx.x] = incl;   // zero-padded tail -> total
}

// phase 2: one warp scans the 49 block totals -> exclusive offsets g_boff
__global__ void k_scan2() {
    int l = threadIdx.x;            // 32 lanes, 2 elements each
    int i0 = 2 * l, i1 = 2 * l + 1;
    int e0 = (i0 < SCAN_NBLK) ? g_bsum[i0] : 0;
    int e1 = (i1 < SCAN_NBLK) ? g_bsum[i1] : 0;
    int p = e0 + e1;
    int x = p;
    #pragma unroll
    for (int o = 1; o < 32; o <<= 1) {
        int y = __shfl_up_sync(0xFFFFFFFFu, x, o);
        if (l >= o) x += y;
    }
    int excl = x - p;
    if (i0 < SCAN_NBLK) g_boff[i0] = excl;
    if (i1 < SCAN_NBLK) g_boff[i1] = excl + e0;
}

// phase 3: add block offsets -> final rowptr, and write cursor copy
__global__ void k_scan3() {
    int i = blockIdx.x * blockDim.x + threadIdx.x;
    if (i >= NN) return;
    int r = g_rowptr[i + 1] + g_boff[i >> 10];
    g_rowptr[i + 1] = r;
    if (i + 1 < NN) g_cursor[i + 1] = r;
    if (i == 0) { g_rowptr[0] = 0; g_cursor[0] = 0; }
}

__global__ void k_fill_csr(const int* __restrict__ src, const int* __restrict__ dst) {
    int i = blockIdx.x * blockDim.x + threadIdx.x;
    if (i >= NEL) return;
    int s, d;
    if (i < NE) { s = src[i]; d = dst[i]; }
    else        { s = d = i - NE; }          // self loop
    int pos = atomicAdd(&g_cursor[d], 1);
    g_csrsrc[pos]  = s;
    g_csrnorm[pos] = g_dinv[s] * g_dinv[d];
}

// ---------------- fp32 tiled GEMM:  C[M x N] = A[M x 128] @ W[128 x N] ----------------
// BM=64, BK=32, TM=4; threads = 256 laid out as 16x16. BN==N (128 or 64).
template <int BN, int TN>
__global__ __launch_bounds__(256)
void k_gemm(const float* __restrict__ A, const float* __restrict__ W,
            float* __restrict__ C, int M, int Ncols) {
    const int K = 128;
    __shared__ float Ast[32][68];   // [k][m], padded
    __shared__ float Bs[32][BN];

    int tid = threadIdx.x;
    int tx = tid & 15;
    int ty = tid >> 4;
    int row0 = blockIdx.x * 64;

    float acc[4][TN];
    #pragma unroll
    for (int i = 0; i < 4; i++)
        #pragma unroll
        for (int j = 0; j < TN; j++) acc[i][j] = 0.f;

    for (int kt = 0; kt < K; kt += 32) {
        #pragma unroll
        for (int i = tid; i < 512; i += 256) {
            int r = i >> 3, c4 = i & 7;
            float4 v = make_float4(0.f, 0.f, 0.f, 0.f);
            if (row0 + r < M)
                v = *(const float4*)&A[(size_t)(row0 + r) * K + kt + c4 * 4];
            Ast[c4 * 4 + 0][r] = v.x;
            Ast[c4 * 4 + 1][r] = v.y;
            Ast[c4 * 4 + 2][r] = v.z;
            Ast[c4 * 4 + 3][r] = v.w;
        }
        #pragma unroll
        for (int i = tid; i < 32 * BN / 4; i += 256) {
            int r = i / (BN / 4), c4 = i % (BN / 4);
            float4 v = *(const float4*)&W[(size_t)(kt + r) * Ncols + c4 * 4];
            *(float4*)&Bs[r][c4 * 4] = v;
        }
        __syncthreads();

        #pragma unroll
        for (int k = 0; k < 32; k++) {
            float4 a = *(const float4*)&Ast[k][ty * 4];
            float av[4] = {a.x, a.y, a.z, a.w};
            float bv[TN];
            #pragma unroll
            for (int j4 = 0; j4 < TN / 4; j4++) {
                float4 b = *(const float4*)&Bs[k][tx * TN + j4 * 4];
                bv[j4 * 4 + 0] = b.x; bv[j4 * 4 + 1] = b.y;
                bv[j4 * 4 + 2] = b.z; bv[j4 * 4 + 3] = b.w;
            }
            #pragma unroll
            for (int i = 0; i < 4; i++)
                #pragma unroll
                for (int j = 0; j < TN; j++)
                    acc[i][j] += av[i] * bv[j];
        }
        __syncthreads();
    }

    #pragma unroll
    for (int i = 0; i < 4; i++) {
        int r = row0 + ty * 4 + i;
        if (r < M) {
            #pragma unroll
            for (int j = 0; j < TN; j++)
                C[(size_t)r * Ncols + tx * TN + j] = acc[i][j];
        }
    }
}

// ---------------- CSR gather-aggregation, float4 lanes + 4-edge software pipeline ----
// out = relu(bias + sum_e norm_e * H[src_e])   — no float atomics.
template <int C>
__global__ __launch_bounds__(128)
void k_agg(const float* __restrict__ H, const float* __restrict__ bias,
           float* __restrict__ out) {
    constexpr int LPN = C / 4;        // lanes per node (32 for C=128, 16 for C=64)
    constexpr int NPB = 128 / LPN;    // nodes per block
    int t = threadIdx.x;
    int ln = t % LPN;
    int node = blockIdx.x * NPB + t / LPN;
    if (node >= NN) return;

    int beg = g_rowptr[node], end = g_rowptr[node + 1];
    float4 acc = ((const float4*)bias)[ln];

    int e = beg;
    for (; e + 4 <= end; e += 4) {
        int s0 = g_csrsrc[e + 0], s1 = g_csrsrc[e + 1];
        int s2 = g_csrsrc[e + 2], s3 = g_csrsrc[e + 3];
        float w0 = g_csrnorm[e + 0], w1 = g_csrnorm[e + 1];
        float w2 = g_csrnorm[e + 2], w3 = g_csrnorm[e + 3];
        float4 h0 = ((const float4*)(H + (size_t)s0 * C))[ln];
        float4 h1 = ((const float4*)(H + (size_t)s1 * C))[ln];
        float4 h2 = ((const float4*)(H + (size_t)s2 * C))[ln];
        float4 h3 = ((const float4*)(H + (size_t)s3 * C))[ln];
        acc.x = fmaf(w0, h0.x, acc.x); acc.y = fmaf(w0, h0.y, acc.y);
        acc.z = fmaf(w0, h0.z, acc.z); acc.w = fmaf(w0, h0.w, acc.w);
        acc.x = fmaf(w1, h1.x, acc.x); acc.y = fmaf(w1, h1.y, acc.y);
        acc.z = fmaf(w1, h1.z, acc.z); acc.w = fmaf(w1, h1.w, acc.w);
        acc.x = fmaf(w2, h2.x, acc.x); acc.y = fmaf(w2, h2.y, acc.y);
        acc.z = fmaf(w2, h2.z, acc.z); acc.w = fmaf(w2, h2.w, acc.w);
        acc.x = fmaf(w3, h3.x, acc.x); acc.y = fmaf(w3, h3.y, acc.y);
        acc.z = fmaf(w3, h3.z, acc.z); acc.w = fmaf(w3, h3.w, acc.w);
    }
    for (; e < end; e++) {
        int s = g_csrsrc[e];
        float w = g_csrnorm[e];
        float4 h = ((const float4*)(H + (size_t)s * C))[ln];
        acc.x = fmaf(w, h.x, acc.x); acc.y = fmaf(w, h.y, acc.y);
        acc.z = fmaf(w, h.z, acc.z); acc.w = fmaf(w, h.w, acc.w);
    }
    acc.x = fmaxf(acc.x, 0.f); acc.y = fmaxf(acc.y, 0.f);
    acc.z = fmaxf(acc.z, 0.f); acc.w = fmaxf(acc.w, 0.f);
    ((float4*)(out + (size_t)node * C))[ln] = acc;
}

// ---------------- fused mean-pool (batch is sorted) + MLP head ----------------
__device__ __forceinline__ int lower_bound_batch(const int* __restrict__ batch, int key) {
    int lo = 0, hi = NN;
    while (lo < hi) {
        int mid = (lo + hi) >> 1;
        if (batch[mid] < key) lo = mid + 1; else hi = mid;
    }
    return lo;
}

__global__ __launch_bounds__(256)
void k_pool_mlp(const float* __restrict__ A, const int* __restrict__ batch,
                const float* __restrict__ demo,
                const float* __restrict__ Wf1, const float* __restrict__ bf1,
                const float* __restrict__ Wf2, const float* __restrict__ bf2,
                const float* __restrict__ Wf3, const float* __restrict__ bf3,
                float* __restrict__ out) {
    int g = blockIdx.x;
    int t = threadIdx.x;                 // 256 threads
    __shared__ int s_beg, s_end;
    __shared__ float sp[4][64];
    __shared__ float z[72];
    __shared__ float z1[64];
    __shared__ float z2[32];

    if (t == 0) s_beg = lower_bound_batch(batch, g);
    if (t == 1) s_end = lower_bound_batch(batch, g + 1);
    __syncthreads();
    int beg = s_beg, end = s_end;

    // mean pool over rows [beg, end), 64 channels, 4 row-groups
    int c = t & 63, rg = t >> 6;
    float acc = 0.f;
    for (int r = beg + rg; r < end; r += 4)
        acc += A[(size_t)r * OUTC + c];
    sp[rg][c] = acc;
    __syncthreads();

    if (t < 64) {
        float s = sp[0][t] + sp[1][t] + sp[2][t] + sp[3][t];
        float invc = 1.f / fmaxf((float)(end - beg), 1.f);
        z[t] = s * invc;
    }
    if (t < DEMO) z[64 + t] = demo[g * DEMO + t];
    __syncthreads();

    if (t < 64) {   // 72 -> 64
        float a = bf1[t];
        #pragma unroll 8
        for (int k = 0; k < 72; k++) a += z[k] * Wf1[k * 64 + t];
        z1[t] = fmaxf(a, 0.f);
    }
    __syncthreads();
    if (t < 32) {   // 64 -> 32
        float a = bf2[t];
        #pragma unroll 8
        for (int k = 0; k < 64; k++) a += z1[k] * Wf2[k * 32 + t];
        z2[t] = fmaxf(a, 0.f);
    }
    __syncthreads();
    if (t < 2) {    // 32 -> 2
        float a = bf3[t];
        #pragma unroll
        for (int k = 0; k < 32; k++) a += z2[k] * Wf3[k * 2 + t];
        out[g * 2 + t] = a;
    }
}

// ---------------- launch ----------------
extern "C" void kernel_launch(void* const* d_in, const int* in_sizes, int n_in,
                              void* d_out, int out_size) {
    const float* x     = (const float*)d_in[0];
    const int*   ei    = (const int*)  d_in[1];   // [2, NE]: src row then dst row
    const int*   batch = (const int*)  d_in[2];
    const float* demo  = (const float*)d_in[3];
    const float* W1 = (const float*)d_in[4];  const float* b1 = (const float*)d_in[5];
    const float* W2 = (const float*)d_in[6];  const float* b2 = (const float*)d_in[7];
    const float* W3 = (const float*)d_in[8];  const float* b3 = (const float*)d_in[9];
    const float* Wf1 = (const float*)d_in[10]; const float* bf1 = (const float*)d_in[11];
    const float* Wf2 = (const float*)d_in[12]; const float* bf2 = (const float*)d_in[13];
    const float* Wf3 = (const float*)d_in[14]; const float* bf3 = (const float*)d_in[15];
    float* out = (float*)d_out;

    const int* src = ei;
    const int* dst = ei + NE;

    float *H, *A;
    cudaGetSymbolAddress((void**)&H, g_H);
    cudaGetSymbolAddress((void**)&A, g_A);

    const int T = 256;
    // --- graph preprocessing ---
    k_deg_init<<<(NN + T - 1) / T, T>>>();
    k_deg_count<<<(NE + T - 1) / T, T>>>(dst);
    k_scan1<<<SCAN_NBLK, SCAN_BLK>>>();            // scan phase 1 + dinv (fused)
    k_scan2<<<1, 32>>>();                          // scan phase 2
    k_scan3<<<(NN + T - 1) / T, T>>>();            // scan phase 3 + cursor
    k_fill_csr<<<(NEL + T - 1) / T, T>>>(src, dst);

    const int gemm_grid = (NN + 63) / 64;   // 782
    // --- layer 1 ---
    k_gemm<128, 8><<<gemm_grid, 256>>>(x, W1, H, NN, HIDC);
    k_agg<128><<<(NN + 3) / 4, 128>>>(H, b1, A);
    // --- layer 2 ---
    k_gemm<128, 8><<<gemm_grid, 256>>>(A, W2, H, NN, HIDC);
    k_agg<128><<<(NN + 3) / 4, 128>>>(H, b2, A);
    // --- layer 3 ---
    k_gemm<64, 4><<<gemm_grid, 256>>>(A, W3, H, NN, OUTC);
    k_agg<64><<<(NN + 7) / 8, 128>>>(H, b3, A);

    // --- fused pooling + MLP head ---
    k_pool_mlp<<<NG, 256>>>(A, batch, demo, Wf1, bf1, Wf2, bf2, Wf3, bf3, out);
}

// round 9
// speedup vs baseline: 2.1087x; 1.5248x over previous
#include <cuda_runtime.h>
#include <cuda_bf16.h>
#include <math.h>
#include <stdint.h>

#define NN   50000      // nodes
#define NE   600000     // edges
#define NEL  (NE + NN)  // edges + self loops
#define NG   100        // graphs
#define OUTC 64
#define DEMO 8

#define NTILES ((NN + 127) / 128)        // 391
#define NPAD   (NTILES * 128)            // 50048

#define SCAN_BLK  1024
#define SCAN_NBLK ((NN + SCAN_BLK - 1) / SCAN_BLK)   // 49

// ---------------- scratch (device globals; no allocation allowed) ----------------
__device__ float g_H[(size_t)NN * 128];           // GEMM output (pre-aggregation)
__device__ float g_A[(size_t)NN * OUTC];          // final layer fp32 (for pooling)
__device__ __nv_bfloat16 g_Xhi[(size_t)NPAD * 128];   // pad rows stay zero
__device__ __nv_bfloat16 g_Xlo[(size_t)NPAD * 128];
__device__ __nv_bfloat16 g_Ahi[(size_t)NPAD * 128];
__device__ __nv_bfloat16 g_Alo[(size_t)NPAD * 128];
__device__ __nv_bfloat16 g_WhiT[128 * 128 * 2 + 64 * 128];   // W1T | W2T | W3T ([n][k])
__device__ __nv_bfloat16 g_WloT[128 * 128 * 2 + 64 * 128];
__device__ int   g_deg[NN];
__device__ int   g_rowptr[NN + 1];
__device__ int   g_cursor[NN];
__device__ int   g_csrsrc[NEL];
__device__ float g_csrnorm[NEL];
__device__ float g_dinv[NN];
__device__ int   g_bsum[SCAN_NBLK];
__device__ int   g_boff[SCAN_NBLK];

// ================= fp32 -> bf16 hi/lo split =================
__device__ __forceinline__ void split_bf16(float v, unsigned short& h, unsigned short& l) {
    __nv_bfloat16 hb = __float2bfloat16(v);
    __nv_bfloat16 lb = __float2bfloat16(v - __bfloat162float(hb));
    h = __bfloat16_as_ushort(hb);
    l = __bfloat16_as_ushort(lb);
}

__global__ void k_convert_x(const float* __restrict__ x) {
    int i = blockIdx.x * blockDim.x + threadIdx.x;   // one float4 chunk
    if (i >= NN * 32) return;
    float4 v = ((const float4*)x)[i];
    unsigned short h0, l0, h1, l1, h2, l2, h3, l3;
    split_bf16(v.x, h0, l0); split_bf16(v.y, h1, l1);
    split_bf16(v.z, h2, l2); split_bf16(v.w, h3, l3);
    uint2 uh, ul;
    uh.x = (uint32_t)h0 | ((uint32_t)h1 << 16);
    uh.y = (uint32_t)h2 | ((uint32_t)h3 << 16);
    ul.x = (uint32_t)l0 | ((uint32_t)l1 << 16);
    ul.y = (uint32_t)l2 | ((uint32_t)l3 << 16);
    ((uint2*)g_Xhi)[i] = uh;
    ((uint2*)g_Xlo)[i] = ul;
}

// transpose + split the three weight matrices into g_W{hi,lo}T ([n][k], k contiguous)
__global__ void k_convert_w(const float* __restrict__ W1, const float* __restrict__ W2,
                            const float* __restrict__ W3) {
    int i = blockIdx.x * blockDim.x + threadIdx.x;   // 0..40959
    if (i >= 40960) return;
    float v;
    if (i < 16384)      { int n = i >> 7,           k = i & 127;           v = W1[k * 128 + n]; }
    else if (i < 32768) { int j = i - 16384; int n = j >> 7, k = j & 127;  v = W2[k * 128 + n]; }
    else                { int j = i - 32768; int n = j >> 7, k = j & 127;  v = W3[k * 64 + n]; }
    unsigned short h, l;
    split_bf16(v, h, l);
    g_WhiT[i] = __ushort_as_bfloat16(h);
    g_WloT[i] = __ushort_as_bfloat16(l);
}

// ================= HMMA bf16 m16n8k16 =================
__device__ __forceinline__ void mma_bf16(float* c, const uint32_t* a, const uint32_t* b) {
    asm volatile(
        "mma.sync.aligned.m16n8k16.row.col.f32.bf16.bf16.f32 "
        "{%0,%1,%2,%3}, {%4,%5,%6,%7}, {%8,%9}, {%0,%1,%2,%3};"
        : "+f"(c[0]), "+f"(c[1]), "+f"(c[2]), "+f"(c[3])
        : "r"(a[0]), "r"(a[1]), "r"(a[2]), "r"(a[3]), "r"(b[0]), "r"(b[1]));
}

// ============ tensor GEMM: H[M x N] = (Ahi+Alo)[M x 128] @ (Bhi+Blo)T,  3-pass compensated ============
// Block: 256 thr = 8 warps; block tile 128 rows x N. B (hi/lo) staged in padded smem.
template <int N>
__global__ __launch_bounds__(256)
void k_gemm_mma(const __nv_bfloat16* __restrict__ Ahi,
                const __nv_bfloat16* __restrict__ Alo,
                const __nv_bfloat16* __restrict__ BhiT,
                const __nv_bfloat16* __restrict__ BloT,
                float* __restrict__ H) {
    constexpr int KS = 136;                    // padded row stride (bf16): 272 B = 17 x 16 B
    constexpr int NT = N / 8;                  // n-tiles per warp
    extern __shared__ __nv_bfloat16 sB[];      // [hi: N*KS][lo: N*KS]
    __nv_bfloat16* sBhi = sB;
    __nv_bfloat16* sBlo = sB + N * KS;

    int tid = threadIdx.x, wid = tid >> 5, lane = tid & 31;

    // stage B: N rows x 128 bf16 (16 uint4 chunks per row)
    for (int i = tid; i < N * 16; i += 256) {
        int n = i >> 4, ch = i & 15;
        *(uint4*)&sBhi[n * KS + ch * 8] = ((const uint4*)BhiT)[n * 16 + ch];
        *(uint4*)&sBlo[n * KS + ch * 8] = ((const uint4*)BloT)[n * 16 + ch];
    }
    __syncthreads();

    int row0 = blockIdx.x * 128 + wid * 16;
    int grp  = lane >> 2;                      // 0..7
    int qk   = (lane & 3) * 2;                 // k-pair offset

    float acc[NT][4];
    #pragma unroll
    for (int j = 0; j < NT; j++)
        #pragma unroll
        for (int q = 0; q < 4; q++) acc[j][q] = 0.f;

    #pragma unroll
    for (int k0 = 0; k0 < 128; k0 += 16) {
        size_t base = (size_t)(row0 + grp) * 128 + k0 + qk;
        uint32_t ah[4], al[4];
        ah[0] = *(const uint32_t*)(Ahi + base);
        ah[1] = *(const uint32_t*)(Ahi + base + 8 * 128);
        ah[2] = *(const uint32_t*)(Ahi + base + 8);
        ah[3] = *(const uint32_t*)(Ahi + base + 8 * 128 + 8);
        al[0] = *(const uint32_t*)(Alo + base);
        al[1] = *(const uint32_t*)(Alo + base + 8 * 128);
        al[2] = *(const uint32_t*)(Alo + base + 8);
        al[3] = *(const uint32_t*)(Alo + base + 8 * 128 + 8);

        #pragma unroll
        for (int j = 0; j < NT; j++) {
            int n = j * 8 + grp;
            uint32_t bh[2], bl[2];
            bh[0] = *(const uint32_t*)&sBhi[n * KS + k0 + qk];
            bh[1] = *(const uint32_t*)&sBhi[n * KS + k0 + qk + 8];
            bl[0] = *(const uint32_t*)&sBlo[n * KS + k0 + qk];
            bl[1] = *(const uint32_t*)&sBlo[n * KS + k0 + qk + 8];
            mma_bf16(acc[j], ah, bh);   // hi*hi
            mma_bf16(acc[j], ah, bl);   // hi*lo
            mma_bf16(acc[j], al, bh);   // lo*hi
        }
    }

    int rc = row0 + grp;
    int cc = (lane & 3) * 2;
    #pragma unroll
    for (int j = 0; j < NT; j++) {
        int col = j * 8 + cc;
        if (rc < NN)
            *(float2*)&H[(size_t)rc * N + col] = make_float2(acc[j][0], acc[j][1]);
        if (rc + 8 < NN)
            *(float2*)&H[(size_t)(rc + 8) * N + col] = make_float2(acc[j][2], acc[j][3]);
    }
}

// ---------------- preprocessing ----------------
__global__ void k_deg_init() {
    int i = blockIdx.x * blockDim.x + threadIdx.x;
    if (i < NN) g_deg[i] = 1;   // self loop
}

__global__ void k_deg_count(const int* __restrict__ dst) {
    int e = blockIdx.x * blockDim.x + threadIdx.x;
    if (e < NE) atomicAdd(&g_deg[dst[e]], 1);
}

__global__ void k_scan1() {
    __shared__ int wsum[32];
    int t = threadIdx.x, lane = t & 31, w = t >> 5;
    int idx = blockIdx.x * SCAN_BLK + t;
    int v = 0;
    if (idx < NN) { v = g_deg[idx]; g_dinv[idx] = rsqrtf((float)v); }
    int x = v;
    #pragma unroll
    for (int o = 1; o < 32; o <<= 1) {
        int y = __shfl_up_sync(0xFFFFFFFFu, x, o);
        if (lane >= o) x += y;
    }
    if (lane == 31) wsum[w] = x;
    __syncthreads();
    if (w == 0) {
        int s = wsum[lane];
        #pragma unroll
        for (int o = 1; o < 32; o <<= 1) {
            int y = __shfl_up_sync(0xFFFFFFFFu, s, o);
            if (lane >= o) s += y;
        }
        wsum[lane] = s;
    }
    __syncthreads();
    int incl = x + (w > 0 ? wsum[w - 1] : 0);
    if (idx < NN) g_rowptr[idx + 1] = incl;
    if (t == SCAN_BLK - 1) g_bsum[blockIdx.x] = incl;
}

__global__ void k_scan2() {
    int l = threadIdx.x;
    int i0 = 2 * l, i1 = 2 * l + 1;
    int e0 = (i0 < SCAN_NBLK) ? g_bsum[i0] : 0;
    int e1 = (i1 < SCAN_NBLK) ? g_bsum[i1] : 0;
    int p = e0 + e1, x = p;
    #pragma unroll
    for (int o = 1; o < 32; o <<= 1) {
        int y = __shfl_up_sync(0xFFFFFFFFu, x, o);
        if (l >= o) x += y;
    }
    int excl = x - p;
    if (i0 < SCAN_NBLK) g_boff[i0] = excl;
    if (i1 < SCAN_NBLK) g_boff[i1] = excl + e0;
}

__global__ void k_scan3() {
    int i = blockIdx.x * blockDim.x + threadIdx.x;
    if (i >= NN) return;
    int r = g_rowptr[i + 1] + g_boff[i >> 10];
    g_rowptr[i + 1] = r;
    if (i + 1 < NN) g_cursor[i + 1] = r;
    if (i == 0) { g_rowptr[0] = 0; g_cursor[0] = 0; }
}

__global__ void k_fill_csr(const int* __restrict__ src, const int* __restrict__ dst) {
    int i = blockIdx.x * blockDim.x + threadIdx.x;
    if (i >= NEL) return;
    int s, d;
    if (i < NE) { s = src[i]; d = dst[i]; }
    else        { s = d = i - NE; }
    int pos = atomicAdd(&g_cursor[d], 1);
    g_csrsrc[pos]  = s;
    g_csrnorm[pos] = g_dinv[s] * g_dinv[d];
}

// ---------------- CSR gather-aggregation (C=128), emits bf16 hi/lo split ----------------
__global__ __launch_bounds__(128)
void k_agg_split(const float* __restrict__ H, const float* __restrict__ bias) {
    const int C = 128, LPN = 32;
    int t = threadIdx.x;
    int ln = t & 31;
    int node = blockIdx.x * 4 + (t >> 5);
    if (node >= NN) return;

    int beg = g_rowptr[node], end = g_rowptr[node + 1];
    float4 acc = ((const float4*)bias)[ln];

    int e = beg;
    for (; e + 4 <= end; e += 4) {
        int s0 = g_csrsrc[e + 0], s1 = g_csrsrc[e + 1];
        int s2 = g_csrsrc[e + 2], s3 = g_csrsrc[e + 3];
        float w0 = g_csrnorm[e + 0], w1 = g_csrnorm[e + 1];
        float w2 = g_csrnorm[e + 2], w3 = g_csrnorm[e + 3];
        float4 h0 = ((const float4*)(H + (size_t)s0 * C))[ln];
        float4 h1 = ((const float4*)(H + (size_t)s1 * C))[ln];
        float4 h2 = ((const float4*)(H + (size_t)s2 * C))[ln];
        float4 h3 = ((const float4*)(H + (size_t)s3 * C))[ln];
        acc.x = fmaf(w0, h0.x, acc.x); acc.y = fmaf(w0, h0.y, acc.y);
        acc.z = fmaf(w0, h0.z, acc.z); acc.w = fmaf(w0, h0.w, acc.w);
        acc.x = fmaf(w1, h1.x, acc.x); acc.y = fmaf(w1, h1.y, acc.y);
        acc.z = fmaf(w1, h1.z, acc.z); acc.w = fmaf(w1, h1.w, acc.w);
        acc.x = fmaf(w2, h2.x, acc.x); acc.y = fmaf(w2, h2.y, acc.y);
        acc.z = fmaf(w2, h2.z, acc.z); acc.w = fmaf(w2, h2.w, acc.w);
        acc.x = fmaf(w3, h3.x, acc.x); acc.y = fmaf(w3, h3.y, acc.y);
        acc.z = fmaf(w3, h3.z, acc.z); acc.w = fmaf(w3, h3.w, acc.w);
    }
    for (; e < end; e++) {
        int s = g_csrsrc[e];
        float w = g_csrnorm[e];
        float4 h = ((const float4*)(H + (size_t)s * C))[ln];
        acc.x = fmaf(w, h.x, acc.x); acc.y = fmaf(w, h.y, acc.y);
        acc.z = fmaf(w, h.z, acc.z); acc.w = fmaf(w, h.w, acc.w);
    }
    acc.x = fmaxf(acc.x, 0.f); acc.y = fmaxf(acc.y, 0.f);
    acc.z = fmaxf(acc.z, 0.f); acc.w = fmaxf(acc.w, 0.f);

    unsigned short h0, l0, h1, l1, h2, l2, h3, l3;
    split_bf16(acc.x, h0, l0); split_bf16(acc.y, h1, l1);
    split_bf16(acc.z, h2, l2); split_bf16(acc.w, h3, l3);
    uint2 uh, ul;
    uh.x = (uint32_t)h0 | ((uint32_t)h1 << 16);
    uh.y = (uint32_t)h2 | ((uint32_t)h3 << 16);
    ul.x = (uint32_t)l0 | ((uint32_t)l1 << 16);
    ul.y = (uint32_t)l2 | ((uint32_t)l3 << 16);
    ((uint2*)g_Ahi)[(size_t)node * LPN + ln] = uh;
    ((uint2*)g_Alo)[(size_t)node * LPN + ln] = ul;
}

// ---------------- CSR gather-aggregation (C=64), fp32 out for pooling ----------------
__global__ __launch_bounds__(128)
void k_agg64(const float* __restrict__ H, const float* __restrict__ bias,
             float* __restrict__ out) {
    const int C = 64, LPN = 16;
    int t = threadIdx.x;
    int ln = t % LPN;
    int node = blockIdx.x * 8 + t / LPN;
    if (node >= NN) return;

    int beg = g_rowptr[node], end = g_rowptr[node + 1];
    float4 acc = ((const float4*)bias)[ln];

    int e = beg;
    for (; e + 4 <= end; e += 4) {
        int s0 = g_csrsrc[e + 0], s1 = g_csrsrc[e + 1];
        int s2 = g_csrsrc[e + 2], s3 = g_csrsrc[e + 3];
        float w0 = g_csrnorm[e + 0], w1 = g_csrnorm[e + 1];
        float w2 = g_csrnorm[e + 2], w3 = g_csrnorm[e + 3];
        float4 h0 = ((const float4*)(H + (size_t)s0 * C))[ln];
        float4 h1 = ((const float4*)(H + (size_t)s1 * C))[ln];
        float4 h2 = ((const float4*)(H + (size_t)s2 * C))[ln];
        float4 h3 = ((const float4*)(H + (size_t)s3 * C))[ln];
        acc.x = fmaf(w0, h0.x, acc.x); acc.y = fmaf(w0, h0.y, acc.y);
        acc.z = fmaf(w0, h0.z, acc.z); acc.w = fmaf(w0, h0.w, acc.w);
        acc.x = fmaf(w1, h1.x, acc.x); acc.y = fmaf(w1, h1.y, acc.y);
        acc.z = fmaf(w1, h1.z, acc.z); acc.w = fmaf(w1, h1.w, acc.w);
        acc.x = fmaf(w2, h2.x, acc.x); acc.y = fmaf(w2, h2.y, acc.y);
        acc.z = fmaf(w2, h2.z, acc.z); acc.w = fmaf(w2, h2.w, acc.w);
        acc.x = fmaf(w3, h3.x, acc.x); acc.y = fmaf(w3, h3.y, acc.y);
        acc.z = fmaf(w3, h3.z, acc.z); acc.w = fmaf(w3, h3.w, acc.w);
    }
    for (; e < end; e++) {
        int s = g_csrsrc[e];
        float w = g_csrnorm[e];
        float4 h = ((const float4*)(H + (size_t)s * C))[ln];
        acc.x = fmaf(w, h.x, acc.x); acc.y = fmaf(w, h.y, acc.y);
        acc.z = fmaf(w, h.z, acc.z); acc.w = fmaf(w, h.w, acc.w);
    }
    acc.x = fmaxf(acc.x, 0.f); acc.y = fmaxf(acc.y, 0.f);
    acc.z = fmaxf(acc.z, 0.f); acc.w = fmaxf(acc.w, 0.f);
    ((float4*)(out + (size_t)node * C))[ln] = acc;
}

// ---------------- fused mean-pool (batch is sorted) + MLP head ----------------
__device__ __forceinline__ int lower_bound_batch(const int* __restrict__ batch, int key) {
    int lo = 0, hi = NN;
    while (lo < hi) {
        int mid = (lo + hi) >> 1;
        if (batch[mid] < key) lo = mid + 1; else hi = mid;
    }
    return lo;
}

__global__ __launch_bounds__(256)
void k_pool_mlp(const float* __restrict__ A, const int* __restrict__ batch,
                const float* __restrict__ demo,
                const float* __restrict__ Wf1, const float* __restrict__ bf1,
                const float* __restrict__ Wf2, const float* __restrict__ bf2,
                const float* __restrict__ Wf3, const float* __restrict__ bf3,
                float* __restrict__ out) {
    int g = blockIdx.x;
    int t = threadIdx.x;
    __shared__ int s_beg, s_end;
    __shared__ float sp[4][64];
    __shared__ float z[72];
    __shared__ float z1[64];
    __shared__ float z2[32];

    if (t == 0) s_beg = lower_bound_batch(batch, g);
    if (t == 1) s_end = lower_bound_batch(batch, g + 1);
    __syncthreads();
    int beg = s_beg, end = s_end;

    int c = t & 63, rg = t >> 6;
    float acc = 0.f;
    for (int r = beg + rg; r < end; r += 4)
        acc += A[(size_t)r * OUTC + c];
    sp[rg][c] = acc;
    __syncthreads();

    if (t < 64) {
        float s = sp[0][t] + sp[1][t] + sp[2][t] + sp[3][t];
        float invc = 1.f / fmaxf((float)(end - beg), 1.f);
        z[t] = s * invc;
    }
    if (t < DEMO) z[64 + t] = demo[g * DEMO + t];
    __syncthreads();

    if (t < 64) {
        float a = bf1[t];
        #pragma unroll 8
        for (int k = 0; k < 72; k++) a += z[k] * Wf1[k * 64 + t];
        z1[t] = fmaxf(a, 0.f);
    }
    __syncthreads();
    if (t < 32) {
        float a = bf2[t];
        #pragma unroll 8
        for (int k = 0; k < 64; k++) a += z1[k] * Wf2[k * 32 + t];
        z2[t] = fmaxf(a, 0.f);
    }
    __syncthreads();
    if (t < 2) {
        float a = bf3[t];
        #pragma unroll
        for (int k = 0; k < 32; k++) a += z2[k] * Wf3[k * 2 + t];
        out[g * 2 + t] = a;
    }
}

// ---------------- launch ----------------
extern "C" void kernel_launch(void* const* d_in, const int* in_sizes, int n_in,
                              void* d_out, int out_size) {
    const float* x     = (const float*)d_in[0];
    const int*   ei    = (const int*)  d_in[1];   // [2, NE]
    const int*   batch = (const int*)  d_in[2];
    const float* demo  = (const float*)d_in[3];
    const float* W1 = (const float*)d_in[4];  const float* b1 = (const float*)d_in[5];
    const float* W2 = (const float*)d_in[6];  const float* b2 = (const float*)d_in[7];
    const float* W3 = (const float*)d_in[8];  const float* b3 = (const float*)d_in[9];
    const float* Wf1 = (const float*)d_in[10]; const float* bf1 = (const float*)d_in[11];
    const float* Wf2 = (const float*)d_in[12]; const float* bf2 = (const float*)d_in[13];
    const float* Wf3 = (const float*)d_in[14]; const float* bf3 = (const float*)d_in[15];
    float* out = (float*)d_out;

    const int* src = ei;
    const int* dst = ei + NE;

    float *H, *A;
    __nv_bfloat16 *Xhi, *Xlo, *Ahi, *Alo, *WhiT, *WloT;
    cudaGetSymbolAddress((void**)&H,    g_H);
    cudaGetSymbolAddress((void**)&A,    g_A);
    cudaGetSymbolAddress((void**)&Xhi,  g_Xhi);
    cudaGetSymbolAddress((void**)&Xlo,  g_Xlo);
    cudaGetSymbolAddress((void**)&Ahi,  g_Ahi);
    cudaGetSymbolAddress((void**)&Alo,  g_Alo);
    cudaGetSymbolAddress((void**)&WhiT, g_WhiT);
    cudaGetSymbolAddress((void**)&WloT, g_WloT);

    // padded-smem sizes: 2 matrices x N rows x 136 bf16 x 2 B
    const int SMEM128 = 2 * 128 * 136 * 2;   // 69632
    const int SMEM64  = 2 * 64  * 136 * 2;   // 34816
    cudaFuncSetAttribute(k_gemm_mma<128>, cudaFuncAttributeMaxDynamicSharedMemorySize, SMEM128);
    cudaFuncSetAttribute(k_gemm_mma<64>,  cudaFuncAttributeMaxDynamicSharedMemorySize, SMEM64);

    const int T = 256;
    // --- graph preprocessing ---
    k_deg_init<<<(NN + T - 1) / T, T>>>();
    k_deg_count<<<(NE + T - 1) / T, T>>>(dst);
    k_scan1<<<SCAN_NBLK, SCAN_BLK>>>();
    k_scan2<<<1, 32>>>();
    k_scan3<<<(NN + T - 1) / T, T>>>();
    k_fill_csr<<<(NEL + T - 1) / T, T>>>(src, dst);

    // --- operand conversion (fp32 -> bf16 hi/lo) ---
    k_convert_w<<<160, 256>>>(W1, W2, W3);
    k_convert_x<<<(NN * 32 + T - 1) / T, T>>>(x);

    // --- layer 1: H = X @ W1 (HMMA, 3-pass compensated), agg -> Ahi/Alo ---
    k_gemm_mma<128><<<NTILES, 256, SMEM128>>>(Xhi, Xlo, WhiT, WloT, H);
    k_agg_split<<<(NN + 3) / 4, 128>>>(H, b1);
    // --- layer 2 ---
    k_gemm_mma<128><<<NTILES, 256, SMEM128>>>(Ahi, Alo, WhiT + 16384, WloT + 16384, H);
    k_agg_split<<<(NN + 3) / 4, 128>>>(H, b2);
    // --- layer 3 (N=64) ---
    k_gemm_mma<64><<<NTILES, 256, SMEM64>>>(Ahi, Alo, WhiT + 32768, WloT + 32768, H);
    k_agg64<<<(NN + 7) / 8, 128>>>(H, b3, A);

    // --- fused pooling + MLP head ---
    k_pool_mlp<<<NG, 256>>>(A, batch, demo, Wf1, bf1, Wf2, bf2, Wf3, bf3, out);
}

// round 10
// speedup vs baseline: 2.2217x; 1.0536x over previous
#include <cuda_runtime.h>
#include <cuda_bf16.h>
#include <cuda_fp16.h>
#include <math.h>
#include <stdint.h>

#define NN   50000      // nodes
#define NE   600000     // edges
#define NEL  (NE + NN)  // edges + self loops
#define NG   100        // graphs
#define OUTC 64
#define DEMO 8

#define NTILES ((NN + 127) / 128)        // 391
#define NPAD   (NTILES * 128)            // 50048

#define SCAN_BLK  1024
#define SCAN_NBLK ((NN + SCAN_BLK - 1) / SCAN_BLK)   // 49

// ---------------- scratch (device globals; no allocation allowed) ----------------
__device__ __half g_H[(size_t)NN * 128];          // GEMM output (fp16, pre-aggregation)
__device__ float g_A[(size_t)NN * OUTC];          // final layer fp32 (for pooling)
__device__ __nv_bfloat16 g_Xhi[(size_t)NPAD * 128];   // pad rows stay zero
__device__ __nv_bfloat16 g_Xlo[(size_t)NPAD * 128];
__device__ __nv_bfloat16 g_Ahi[(size_t)NPAD * 128];
__device__ __nv_bfloat16 g_Alo[(size_t)NPAD * 128];
__device__ __nv_bfloat16 g_WhiT[128 * 128 * 2 + 64 * 128];   // W1T | W2T | W3T ([n][k])
__device__ __nv_bfloat16 g_WloT[128 * 128 * 2 + 64 * 128];
__device__ int   g_deg[NN];
__device__ int   g_rowptr[NN + 1];
__device__ int   g_cursor[NN];
__device__ int   g_csrsrc[NEL];
__device__ float g_csrnorm[NEL];
__device__ float g_dinv[NN];
__device__ int   g_bsum[SCAN_NBLK];

// ================= fp32 -> bf16 hi/lo split =================
__device__ __forceinline__ void split_bf16(float v, unsigned short& h, unsigned short& l) {
    __nv_bfloat16 hb = __float2bfloat16(v);
    __nv_bfloat16 lb = __float2bfloat16(v - __bfloat162float(hb));
    h = __bfloat16_as_ushort(hb);
    l = __bfloat16_as_ushort(lb);
}

// fused: deg init + x split-convert + W transpose/split-convert (all independent elementwise)
__global__ void k_prep(const float* __restrict__ x,
                       const float* __restrict__ W1, const float* __restrict__ W2,
                       const float* __restrict__ W3) {
    int i = blockIdx.x * blockDim.x + threadIdx.x;
    if (i < NN) g_deg[i] = 1;                    // self loop
    if (i < 40960) {                             // weight transpose + split
        float v;
        if (i < 16384)      { int n = i >> 7,           k = i & 127;          v = W1[k * 128 + n]; }
        else if (i < 32768) { int j = i - 16384; int n = j >> 7, k = j & 127; v = W2[k * 128 + n]; }
        else                { int j = i - 32768; int n = j >> 7, k = j & 127; v = W3[k * 64 + n]; }
        unsigned short h, l;
        split_bf16(v, h, l);
        g_WhiT[i] = __ushort_as_bfloat16(h);
        g_WloT[i] = __ushort_as_bfloat16(l);
    }
    if (i < NN * 32) {                           // x split (one float4 chunk)
        float4 v = ((const float4*)x)[i];
        unsigned short h0, l0, h1, l1, h2, l2, h3, l3;
        split_bf16(v.x, h0, l0); split_bf16(v.y, h1, l1);
        split_bf16(v.z, h2, l2); split_bf16(v.w, h3, l3);
        uint2 uh, ul;
        uh.x = (uint32_t)h0 | ((uint32_t)h1 << 16);
        uh.y = (uint32_t)h2 | ((uint32_t)h3 << 16);
        ul.x = (uint32_t)l0 | ((uint32_t)l1 << 16);
        ul.y = (uint32_t)l2 | ((uint32_t)l3 << 16);
        ((uint2*)g_Xhi)[i] = uh;
        ((uint2*)g_Xlo)[i] = ul;
    }
}

// ================= HMMA bf16 m16n8k16 =================
__device__ __forceinline__ void mma_bf16(float* c, const uint32_t* a, const uint32_t* b) {
    asm volatile(
        "mma.sync.aligned.m16n8k16.row.col.f32.bf16.bf16.f32 "
        "{%0,%1,%2,%3}, {%4,%5,%6,%7}, {%8,%9}, {%0,%1,%2,%3};"
        : "+f"(c[0]), "+f"(c[1]), "+f"(c[2]), "+f"(c[3])
        : "r"(a[0]), "r"(a[1]), "r"(a[2]), "r"(a[3]), "r"(b[0]), "r"(b[1]));
}

// ============ tensor GEMM: H[M x N] = (Ahi+Alo)[M x 128] @ (Bhi+Blo)T,  3-pass compensated ============
// Block: 256 thr = 8 warps; block tile 128 rows x N. B (hi/lo) staged in padded smem. fp16 output.
template <int N>
__global__ __launch_bounds__(256)
void k_gemm_mma(const __nv_bfloat16* __restrict__ Ahi,
                const __nv_bfloat16* __restrict__ Alo,
                const __nv_bfloat16* __restrict__ BhiT,
                const __nv_bfloat16* __restrict__ BloT,
                __half* __restrict__ H) {
    constexpr int KS = 136;                    // padded row stride (bf16): 272 B = 17 x 16 B
    constexpr int NT = N / 8;                  // n-tiles per warp
    extern __shared__ __nv_bfloat16 sB[];      // [hi: N*KS][lo: N*KS]
    __nv_bfloat16* sBhi = sB;
    __nv_bfloat16* sBlo = sB + N * KS;

    int tid = threadIdx.x, wid = tid >> 5, lane = tid & 31;

    // stage B: N rows x 128 bf16 (16 uint4 chunks per row)
    for (int i = tid; i < N * 16; i += 256) {
        int n = i >> 4, ch = i & 15;
        *(uint4*)&sBhi[n * KS + ch * 8] = ((const uint4*)BhiT)[n * 16 + ch];
        *(uint4*)&sBlo[n * KS + ch * 8] = ((const uint4*)BloT)[n * 16 + ch];
    }
    __syncthreads();

    int row0 = blockIdx.x * 128 + wid * 16;
    int grp  = lane >> 2;                      // 0..7
    int qk   = (lane & 3) * 2;                 // k-pair offset

    float acc[NT][4];
    #pragma unroll
    for (int j = 0; j < NT; j++)
        #pragma unroll
        for (int q = 0; q < 4; q++) acc[j][q] = 0.f;

    #pragma unroll
    for (int k0 = 0; k0 < 128; k0 += 16) {
        size_t base = (size_t)(row0 + grp) * 128 + k0 + qk;
        uint32_t ah[4], al[4];
        ah[0] = *(const uint32_t*)(Ahi + base);
        ah[1] = *(const uint32_t*)(Ahi + base + 8 * 128);
        ah[2] = *(const uint32_t*)(Ahi + base + 8);
        ah[3] = *(const uint32_t*)(Ahi + base + 8 * 128 + 8);
        al[0] = *(const uint32_t*)(Alo + base);
        al[1] = *(const uint32_t*)(Alo + base + 8 * 128);
        al[2] = *(const uint32_t*)(Alo + base + 8);
        al[3] = *(const uint32_t*)(Alo + base + 8 * 128 + 8);

        #pragma unroll
        for (int j = 0; j < NT; j++) {
            int n = j * 8 + grp;
            uint32_t bh[2], bl[2];
            bh[0] = *(const uint32_t*)&sBhi[n * KS + k0 + qk];
            bh[1] = *(const uint32_t*)&sBhi[n * KS + k0 + qk + 8];
            bl[0] = *(const uint32_t*)&sBlo[n * KS + k0 + qk];
            bl[1] = *(const uint32_t*)&sBlo[n * KS + k0 + qk + 8];
            mma_bf16(acc[j], ah, bh);   // hi*hi
            mma_bf16(acc[j], ah, bl);   // hi*lo
            mma_bf16(acc[j], al, bh);   // lo*hi
        }
    }

    int rc = row0 + grp;
    int cc = (lane & 3) * 2;
    #pragma unroll
    for (int j = 0; j < NT; j++) {
        int col = j * 8 + cc;
        if (rc < NN)
            *(__half2*)&H[(size_t)rc * N + col] = __floats2half2_rn(acc[j][0], acc[j][1]);
        if (rc + 8 < NN)
            *(__half2*)&H[(size_t)(rc + 8) * N + col] = __floats2half2_rn(acc[j][2], acc[j][3]);
    }
}

// ---------------- preprocessing ----------------
__global__ void k_deg_count(const int* __restrict__ dst) {
    int e = blockIdx.x * blockDim.x + threadIdx.x;
    if (e < NE) atomicAdd(&g_deg[dst[e]], 1);
}

__global__ void k_scan1() {
    __shared__ int wsum[32];
    int t = threadIdx.x, lane = t & 31, w = t >> 5;
    int idx = blockIdx.x * SCAN_BLK + t;
    int v = 0;
    if (idx < NN) { v = g_deg[idx]; g_dinv[idx] = rsqrtf((float)v); }
    int x = v;
    #pragma unroll
    for (int o = 1; o < 32; o <<= 1) {
        int y = __shfl_up_sync(0xFFFFFFFFu, x, o);
        if (lane >= o) x += y;
    }
    if (lane == 31) wsum[w] = x;
    __syncthreads();
    if (w == 0) {
        int s = wsum[lane];
        #pragma unroll
        for (int o = 1; o < 32; o <<= 1) {
            int y = __shfl_up_sync(0xFFFFFFFFu, s, o);
            if (lane >= o) s += y;
        }
        wsum[lane] = s;
    }
    __syncthreads();
    int incl = x + (w > 0 ? wsum[w - 1] : 0);
    if (idx < NN) g_rowptr[idx + 1] = incl;
    if (t == SCAN_BLK - 1) g_bsum[blockIdx.x] = incl;
}

// scan3 with inlined scan2: warp 0 scans the 49 block sums redundantly per block
__global__ void k_scan3() {
    __shared__ int sboff[SCAN_NBLK];
    int t = threadIdx.x;
    if (t < 32) {
        int i0 = 2 * t, i1 = 2 * t + 1;
        int e0 = (i0 < SCAN_NBLK) ? g_bsum[i0] : 0;
        int e1 = (i1 < SCAN_NBLK) ? g_bsum[i1] : 0;
        int p = e0 + e1, x = p;
        #pragma unroll
        for (int o = 1; o < 32; o <<= 1) {
            int y = __shfl_up_sync(0xFFFFFFFFu, x, o);
            if (t >= o) x += y;
        }
        int excl = x - p;
        if (i0 < SCAN_NBLK) sboff[i0] = excl;
        if (i1 < SCAN_NBLK) sboff[i1] = excl + e0;
    }
    __syncthreads();
    int i = blockIdx.x * blockDim.x + t;
    if (i >= NN) return;
    int r = g_rowptr[i + 1] + sboff[i >> 10];
    g_rowptr[i + 1] = r;
    if (i + 1 < NN) g_cursor[i + 1] = r;
    if (i == 0) { g_rowptr[0] = 0; g_cursor[0] = 0; }
}

__global__ void k_fill_csr(const int* __restrict__ src, const int* __restrict__ dst) {
    int i = blockIdx.x * blockDim.x + threadIdx.x;
    if (i >= NEL) return;
    int s, d;
    if (i < NE) { s = src[i]; d = dst[i]; }
    else        { s = d = i - NE; }
    int pos = atomicAdd(&g_cursor[d], 1);
    g_csrsrc[pos]  = s;
    g_csrnorm[pos] = g_dinv[s] * g_dinv[d];
}

// ---------------- CSR gather-aggregation (C=128, fp16 H), emits bf16 hi/lo split ----------------
__device__ __forceinline__ float4 ld_h4(const __half* __restrict__ H, size_t row, int C, int ln) {
    __half2 h2[2];
    *(uint2*)h2 = *(const uint2*)(H + row * C + 4 * ln);
    float2 f01 = __half22float2(h2[0]);
    float2 f23 = __half22float2(h2[1]);
    return make_float4(f01.x, f01.y, f23.x, f23.y);
}

__global__ __launch_bounds__(128)
void k_agg_split(const __half* __restrict__ H, const float* __restrict__ bias) {
    const int C = 128, LPN = 32;
    int t = threadIdx.x;
    int ln = t & 31;
    int node = blockIdx.x * 4 + (t >> 5);
    if (node >= NN) return;

    int beg = g_rowptr[node], end = g_rowptr[node + 1];
    float4 acc = ((const float4*)bias)[ln];

    int e = beg;
    for (; e + 4 <= end; e += 4) {
        int s0 = g_csrsrc[e + 0], s1 = g_csrsrc[e + 1];
        int s2 = g_csrsrc[e + 2], s3 = g_csrsrc[e + 3];
        float w0 = g_csrnorm[e + 0], w1 = g_csrnorm[e + 1];
        float w2 = g_csrnorm[e + 2], w3 = g_csrnorm[e + 3];
        float4 h0 = ld_h4(H, (size_t)s0, C, ln);
        float4 h1 = ld_h4(H, (size_t)s1, C, ln);
        float4 h2 = ld_h4(H, (size_t)s2, C, ln);
        float4 h3 = ld_h4(H, (size_t)s3, C, ln);
        acc.x = fmaf(w0, h0.x, acc.x); acc.y = fmaf(w0, h0.y, acc.y);
        acc.z = fmaf(w0, h0.z, acc.z); acc.w = fmaf(w0, h0.w, acc.w);
        acc.x = fmaf(w1, h1.x, acc.x); acc.y = fmaf(w1, h1.y, acc.y);
        acc.z = fmaf(w1, h1.z, acc.z); acc.w = fmaf(w1, h1.w, acc.w);
        acc.x = fmaf(w2, h2.x, acc.x); acc.y = fmaf(w2, h2.y, acc.y);
        acc.z = fmaf(w2, h2.z, acc.z); acc.w = fmaf(w2, h2.w, acc.w);
        acc.x = fmaf(w3, h3.x, acc.x); acc.y = fmaf(w3, h3.y, acc.y);
        acc.z = fmaf(w3, h3.z, acc.z); acc.w = fmaf(w3, h3.w, acc.w);
    }
    for (; e < end; e++) {
        int s = g_csrsrc[e];
        float w = g_csrnorm[e];
        float4 h = ld_h4(H, (size_t)s, C, ln);
        acc.x = fmaf(w, h.x, acc.x); acc.y = fmaf(w, h.y, acc.y);
        acc.z = fmaf(w, h.z, acc.z); acc.w = fmaf(w, h.w, acc.w);
    }
    acc.x = fmaxf(acc.x, 0.f); acc.y = fmaxf(acc.y, 0.f);
    acc.z = fmaxf(acc.z, 0.f); acc.w = fmaxf(acc.w, 0.f);

    unsigned short h0, l0, h1, l1, h2, l2, h3, l3;
    split_bf16(acc.x, h0, l0); split_bf16(acc.y, h1, l1);
    split_bf16(acc.z, h2, l2); split_bf16(acc.w, h3, l3);
    uint2 uh, ul;
    uh.x = (uint32_t)h0 | ((uint32_t)h1 << 16);
    uh.y = (uint32_t)h2 | ((uint32_t)h3 << 16);
    ul.x = (uint32_t)l0 | ((uint32_t)l1 << 16);
    ul.y = (uint32_t)l2 | ((uint32_t)l3 << 16);
    ((uint2*)g_Ahi)[(size_t)node * LPN + ln] = uh;
    ((uint2*)g_Alo)[(size_t)node * LPN + ln] = ul;
}

// ---------------- CSR gather-aggregation (C=64, fp16 H), fp32 out for pooling ----------------
__global__ __launch_bounds__(128)
void k_agg64(const __half* __restrict__ H, const float* __restrict__ bias,
             float* __restrict__ out) {
    const int C = 64, LPN = 16;
    int t = threadIdx.x;
    int ln = t % LPN;
    int node = blockIdx.x * 8 + t / LPN;
    if (node >= NN) return;

    int beg = g_rowptr[node], end = g_rowptr[node + 1];
    float4 acc = ((const float4*)bias)[ln];

    int e = beg;
    for (; e + 4 <= end; e += 4) {
        int s0 = g_csrsrc[e + 0], s1 = g_csrsrc[e + 1];
        int s2 = g_csrsrc[e + 2], s3 = g_csrsrc[e + 3];
        float w0 = g_csrnorm[e + 0], w1 = g_csrnorm[e + 1];
        float w2 = g_csrnorm[e + 2], w3 = g_csrnorm[e + 3];
        float4 h0 = ld_h4(H, (size_t)s0, C, ln);
        float4 h1 = ld_h4(H, (size_t)s1, C, ln);
        float4 h2 = ld_h4(H, (size_t)s2, C, ln);
        float4 h3 = ld_h4(H, (size_t)s3, C, ln);
        acc.x = fmaf(w0, h0.x, acc.x); acc.y = fmaf(w0, h0.y, acc.y);
        acc.z = fmaf(w0, h0.z, acc.z); acc.w = fmaf(w0, h0.w, acc.w);
        acc.x = fmaf(w1, h1.x, acc.x); acc.y = fmaf(w1, h1.y, acc.y);
        acc.z = fmaf(w1, h1.z, acc.z); acc.w = fmaf(w1, h1.w, acc.w);
        acc.x = fmaf(w2, h2.x, acc.x); acc.y = fmaf(w2, h2.y, acc.y);
        acc.z = fmaf(w2, h2.z, acc.z); acc.w = fmaf(w2, h2.w, acc.w);
        acc.x = fmaf(w3, h3.x, acc.x); acc.y = fmaf(w3, h3.y, acc.y);
        acc.z = fmaf(w3, h3.z, acc.z); acc.w = fmaf(w3, h3.w, acc.w);
    }
    for (; e < end; e++) {
        int s = g_csrsrc[e];
        float w = g_csrnorm[e];
        float4 h = ld_h4(H, (size_t)s, C, ln);
        acc.x = fmaf(w, h.x, acc.x); acc.y = fmaf(w, h.y, acc.y);
        acc.z = fmaf(w, h.z, acc.z); acc.w = fmaf(w, h.w, acc.w);
    }
    acc.x = fmaxf(acc.x, 0.f); acc.y = fmaxf(acc.y, 0.f);
    acc.z = fmaxf(acc.z, 0.f); acc.w = fmaxf(acc.w, 0.f);
    ((float4*)(out + (size_t)node * C))[ln] = acc;
}

// ---------------- fused mean-pool (batch is sorted) + MLP head ----------------
__device__ __forceinline__ int lower_bound_batch(const int* __restrict__ batch, int key) {
    int lo = 0, hi = NN;
    while (lo < hi) {
        int mid = (lo + hi) >> 1;
        if (batch[mid] < key) lo = mid + 1; else hi = mid;
    }
    return lo;
}

__global__ __launch_bounds__(256)
void k_pool_mlp(const float* __restrict__ A, const int* __restrict__ batch,
                const float* __restrict__ demo,
                const float* __restrict__ Wf1, const float* __restrict__ bf1,
                const float* __restrict__ Wf2, const float* __restrict__ bf2,
                const float* __restrict__ Wf3, const float* __restrict__ bf3,
                float* __restrict__ out) {
    int g = blockIdx.x;
    int t = threadIdx.x;
    __shared__ int s_beg, s_end;
    __shared__ float sp[4][64];
    __shared__ float z[72];
    __shared__ float z1[64];
    __shared__ float z2[32];

    if (t == 0) s_beg = lower_bound_batch(batch, g);
    if (t == 1) s_end = lower_bound_batch(batch, g + 1);
    __syncthreads();
    int beg = s_beg, end = s_end;

    int c = t & 63, rg = t >> 6;
    float acc = 0.f;
    for (int r = beg + rg; r < end; r += 4)
        acc += A[(size_t)r * OUTC + c];
    sp[rg][c] = acc;
    __syncthreads();

    if (t < 64) {
        float s = sp[0][t] + sp[1][t] + sp[2][t] + sp[3][t];
        float invc = 1.f / fmaxf((float)(end - beg), 1.f);
        z[t] = s * invc;
    }
    if (t < DEMO) z[64 + t] = demo[g * DEMO + t];
    __syncthreads();

    if (t < 64) {
        float a = bf1[t];
        #pragma unroll 8
        for (int k = 0; k < 72; k++) a += z[k] * Wf1[k * 64 + t];
        z1[t] = fmaxf(a, 0.f);
    }
    __syncthreads();
    if (t < 32) {
        float a = bf2[t];
        #pragma unroll 8
        for (int k = 0; k < 64; k++) a += z1[k] * Wf2[k * 32 + t];
        z2[t] = fmaxf(a, 0.f);
    }
    __syncthreads();
    if (t < 2) {
        float a = bf3[t];
        #pragma unroll
        for (int k = 0; k < 32; k++) a += z2[k] * Wf3[k * 2 + t];
        out[g * 2 + t] = a;
    }
}

// ---------------- launch ----------------
extern "C" void kernel_launch(void* const* d_in, const int* in_sizes, int n_in,
                              void* d_out, int out_size) {
    const float* x     = (const float*)d_in[0];
    const int*   ei    = (const int*)  d_in[1];   // [2, NE]
    const int*   batch = (const int*)  d_in[2];
    const float* demo  = (const float*)d_in[3];
    const float* W1 = (const float*)d_in[4];  const float* b1 = (const float*)d_in[5];
    const float* W2 = (const float*)d_in[6];  const float* b2 = (const float*)d_in[7];
    const float* W3 = (const float*)d_in[8];  const float* b3 = (const float*)d_in[9];
    const float* Wf1 = (const float*)d_in[10]; const float* bf1 = (const float*)d_in[11];
    const float* Wf2 = (const float*)d_in[12]; const float* bf2 = (const float*)d_in[13];
    const float* Wf3 = (const float*)d_in[14]; const float* bf3 = (const float*)d_in[15];
    float* out = (float*)d_out;

    const int* src = ei;
    const int* dst = ei + NE;

    float *A;
    __half *H;
    __nv_bfloat16 *Xhi, *Xlo, *Ahi, *Alo, *WhiT, *WloT;
    cudaGetSymbolAddress((void**)&H,    g_H);
    cudaGetSymbolAddress((void**)&A,    g_A);
    cudaGetSymbolAddress((void**)&Xhi,  g_Xhi);
    cudaGetSymbolAddress((void**)&Xlo,  g_Xlo);
    cudaGetSymbolAddress((void**)&Ahi,  g_Ahi);
    cudaGetSymbolAddress((void**)&Alo,  g_Alo);
    cudaGetSymbolAddress((void**)&WhiT, g_WhiT);
    cudaGetSymbolAddress((void**)&WloT, g_WloT);

    // padded-smem sizes: 2 matrices x N rows x 136 bf16 x 2 B
    const int SMEM128 = 2 * 128 * 136 * 2;   // 69632
    const int SMEM64  = 2 * 64  * 136 * 2;   // 34816
    cudaFuncSetAttribute(k_gemm_mma<128>, cudaFuncAttributeMaxDynamicSharedMemorySize, SMEM128);
    cudaFuncSetAttribute(k_gemm_mma<64>,  cudaFuncAttributeMaxDynamicSharedMemorySize, SMEM64);

    const int T = 256;
    // --- fused prep: deg init + x split + W transpose/split ---
    k_prep<<<(NN * 32 + T - 1) / T, T>>>(x, W1, W2, W3);
    // --- graph preprocessing ---
    k_deg_count<<<(NE + T - 1) / T, T>>>(dst);
    k_scan1<<<SCAN_NBLK, SCAN_BLK>>>();
    k_scan3<<<(NN + T - 1) / T, T>>>();           // includes inlined block-sum scan
    k_fill_csr<<<(NEL + T - 1) / T, T>>>(src, dst);

    // --- layer 1: H = X @ W1 (HMMA, 3-pass compensated, fp16 out), agg -> Ahi/Alo ---
    k_gemm_mma<128><<<NTILES, 256, SMEM128>>>(Xhi, Xlo, WhiT, WloT, H);
    k_agg_split<<<(NN + 3) / 4, 128>>>(H, b1);
    // --- layer 2 ---
    k_gemm_mma<128><<<NTILES, 256, SMEM128>>>(Ahi, Alo, WhiT + 16384, WloT + 16384, H);
    k_agg_split<<<(NN + 3) / 4, 128>>>(H, b2);
    // --- layer 3 (N=64) ---
    k_gemm_mma<64><<<NTILES, 256, SMEM64>>>(Ahi, Alo, WhiT + 32768, WloT + 32768, H);
    k_agg64<<<(NN + 7) / 8, 128>>>(H, b3, A);

    // --- fused pooling + MLP head ---
    k_pool_mlp<<<NG, 256>>>(A, batch, demo, Wf1, bf1, Wf2, bf2, Wf3, bf3, out);
}

// round 11
// speedup vs baseline: 2.5265x; 1.1372x over previous
#include <cuda_runtime.h>
#include <cuda_bf16.h>
#include <math.h>
#include <stdint.h>

#define NN   50000      // nodes
#define NE   600000     // edges
#define NEL  (NE + NN)  // edges + self loops
#define NG   100        // graphs
#define OUTC 64
#define DEMO 8

#define NTILES ((NN + 127) / 128)        // 391
#define NPAD   (NTILES * 128)            // 50048

#define SCAN_BLK  1024
#define SCAN_NBLK ((NN + SCAN_BLK - 1) / SCAN_BLK)   // 49

// W interleaved chunks (uint4): L1 8*128*4=4096, L2 4096, L3 8*64*4=2048
#define WC_L2 4096
#define WC_L3 8192
#define WC_TOT 10240

// ---------------- scratch (device globals; zero-init at load; no allocation) ----------------
__device__ __nv_bfloat16 g_Xb[(size_t)NN * 128];    // bf16 input features
__device__ __nv_bfloat16 g_Ab[(size_t)NN * 128];    // GEMM bf16 output (layers 1,2)
__device__ __nv_bfloat16 g_G[(size_t)NPAD * 128];   // agg output = GEMM input; pad rows stay 0
__device__ float g_A[(size_t)NN * OUTC];            // final layer fp32 (for pooling)
__device__ uint4 g_Wint[WC_TOT];                    // interleaved W fragments (hi/lo)
__device__ int   g_deg[NN];                         // self-zeroed each call by k_scan1
__device__ int   g_rowptr[NN + 1];
__device__ int   g_cursor[NN];
__device__ int2  g_csr[NEL];                        // {src, norm_bits}
__device__ float g_dinv[NN];
__device__ int   g_bsum[SCAN_NBLK];

// ================= fp32 -> bf16 hi/lo split =================
__device__ __forceinline__ void split_bf16(float v, unsigned short& h, unsigned short& l) {
    __nv_bfloat16 hb = __float2bfloat16(v);
    __nv_bfloat16 lb = __float2bfloat16(v - __bfloat162float(hb));
    h = __bfloat16_as_ushort(hb);
    l = __bfloat16_as_ushort(lb);
}

// fused prep: edge degree count + x->bf16 + W interleave/split. Independent elementwise parts.
__global__ void k_prep(const float* __restrict__ x,
                       const float* __restrict__ W1, const float* __restrict__ W2,
                       const float* __restrict__ W3, const int* __restrict__ dst) {
    int i = blockIdx.x * blockDim.x + threadIdx.x;

    if (i < NE) atomicAdd(&g_deg[dst[i]], 1);       // deg starts 0 (zeroed by prior scan1)

    if (i < WC_TOT * 4) {                            // one word of one W chunk
        int c = i >> 2, s = i & 3;
        const float* Wsrc; int Ncols; int cl = c;
        if (cl < WC_L2)      { Wsrc = W1; Ncols = 128; }
        else if (cl < WC_L3) { Wsrc = W2; Ncols = 128; cl -= WC_L2; }
        else                 { Wsrc = W3; Ncols = 64;  cl -= WC_L3; }
        int q = cl & 3, rest = cl >> 2;
        int n = rest % Ncols, k08 = rest / Ncols;
        int kb = k08 * 16 + 2 * q + ((s & 1) ? 8 : 0);
        float v0 = Wsrc[kb * Ncols + n];
        float v1 = Wsrc[(kb + 1) * Ncols + n];
        unsigned short h0, l0, h1, l1;
        split_bf16(v0, h0, l0);
        split_bf16(v1, h1, l1);
        uint32_t w = (s < 2) ? ((uint32_t)h0 | ((uint32_t)h1 << 16))
                             : ((uint32_t)l0 | ((uint32_t)l1 << 16));
        ((uint32_t*)g_Wint)[i] = w;
    }

    if (i < NN * 32) {                               // x: one float4 -> 4 bf16
        float4 v = ((const float4*)x)[i];
        __nv_bfloat16 b0 = __float2bfloat16(v.x), b1 = __float2bfloat16(v.y);
        __nv_bfloat16 b2 = __float2bfloat16(v.z), b3 = __float2bfloat16(v.w);
        uint2 u;
        u.x = (uint32_t)__bfloat16_as_ushort(b0) | ((uint32_t)__bfloat16_as_ushort(b1) << 16);
        u.y = (uint32_t)__bfloat16_as_ushort(b2) | ((uint32_t)__bfloat16_as_ushort(b3) << 16);
        ((uint2*)g_Xb)[i] = u;
    }
}

// ---------------- scan phase 1: block-local inclusive scan of (deg+1); self-zero deg ----------------
__global__ void k_scan1() {
    __shared__ int wsum[32];
    int t = threadIdx.x, lane = t & 31, w = t >> 5;
    int idx = blockIdx.x * SCAN_BLK + t;
    int v = 0;
    if (idx < NN) {
        int d = g_deg[idx];
        g_deg[idx] = 0;                      // reset for next graph replay
        v = d + 1;                           // + self loop
        g_dinv[idx] = rsqrtf((float)v);
    }
    int x = v;
    #pragma unroll
    for (int o = 1; o < 32; o <<= 1) {
        int y = __shfl_up_sync(0xFFFFFFFFu, x, o);
        if (lane >= o) x += y;
    }
    if (lane == 31) wsum[w] = x;
    __syncthreads();
    if (w == 0) {
        int s = wsum[lane];
        #pragma unroll
        for (int o = 1; o < 32; o <<= 1) {
            int y = __shfl_up_sync(0xFFFFFFFFu, s, o);
            if (lane >= o) s += y;
        }
        wsum[lane] = s;
    }
    __syncthreads();
    int incl = x + (w > 0 ? wsum[w - 1] : 0);
    if (idx < NN) g_rowptr[idx + 1] = incl;
    if (t == SCAN_BLK - 1) g_bsum[blockIdx.x] = incl;
}

// scan phase 3 (with inlined phase-2 scan of 49 block sums) + cursor init
__global__ void k_scan3() {
    __shared__ int sboff[SCAN_NBLK];
    int t = threadIdx.x;
    if (t < 32) {
        int i0 = 2 * t, i1 = 2 * t + 1;
        int e0 = (i0 < SCAN_NBLK) ? g_bsum[i0] : 0;
        int e1 = (i1 < SCAN_NBLK) ? g_bsum[i1] : 0;
        int p = e0 + e1, x = p;
        #pragma unroll
        for (int o = 1; o < 32; o <<= 1) {
            int y = __shfl_up_sync(0xFFFFFFFFu, x, o);
            if (t >= o) x += y;
        }
        int excl = x - p;
        if (i0 < SCAN_NBLK) sboff[i0] = excl;
        if (i1 < SCAN_NBLK) sboff[i1] = excl + e0;
    }
    __syncthreads();
    int i = blockIdx.x * blockDim.x + t;
    if (i >= NN) return;
    int r = g_rowptr[i + 1] + sboff[i >> 10];
    g_rowptr[i + 1] = r;
    if (i + 1 < NN) g_cursor[i + 1] = r;
    if (i == 0) { g_rowptr[0] = 0; g_cursor[0] = 0; }
}

__global__ void k_fill_csr(const int* __restrict__ src, const int* __restrict__ dst) {
    int i = blockIdx.x * blockDim.x + threadIdx.x;
    if (i >= NEL) return;
    int s, d;
    if (i < NE) { s = src[i]; d = dst[i]; }
    else        { s = d = i - NE; }
    int pos = atomicAdd(&g_cursor[d], 1);
    g_csr[pos] = make_int2(s, __float_as_int(g_dinv[s] * g_dinv[d]));
}

// ---------------- CSR gather-aggregation: G[node] = sum_e norm_e * X[src_e]  (bf16 in/out) ----------------
__global__ __launch_bounds__(256)
void k_agg(const __nv_bfloat16* __restrict__ X) {
    int t = threadIdx.x, ln = t & 31;
    int node = blockIdx.x * 8 + (t >> 5);
    if (node >= NN) return;

    int beg = g_rowptr[node], end = g_rowptr[node + 1];
    float4 acc = make_float4(0.f, 0.f, 0.f, 0.f);

    int e = beg;
    for (; e + 4 <= end; e += 4) {
        int2 m0 = g_csr[e + 0], m1 = g_csr[e + 1];
        int2 m2 = g_csr[e + 2], m3 = g_csr[e + 3];
        uint2 u0 = ((const uint2*)(X + (size_t)m0.x * 128))[ln];
        uint2 u1 = ((const uint2*)(X + (size_t)m1.x * 128))[ln];
        uint2 u2 = ((const uint2*)(X + (size_t)m2.x * 128))[ln];
        uint2 u3 = ((const uint2*)(X + (size_t)m3.x * 128))[ln];
        float w0 = __int_as_float(m0.y), w1 = __int_as_float(m1.y);
        float w2 = __int_as_float(m2.y), w3 = __int_as_float(m3.y);
        float2 a0 = __bfloat1622float2(*(__nv_bfloat162*)&u0.x);
        float2 b0 = __bfloat1622float2(*(__nv_bfloat162*)&u0.y);
        float2 a1 = __bfloat1622float2(*(__nv_bfloat162*)&u1.x);
        float2 b1 = __bfloat1622float2(*(__nv_bfloat162*)&u1.y);
        float2 a2 = __bfloat1622float2(*(__nv_bfloat162*)&u2.x);
        float2 b2 = __bfloat1622float2(*(__nv_bfloat162*)&u2.y);
        float2 a3 = __bfloat1622float2(*(__nv_bfloat162*)&u3.x);
        float2 b3 = __bfloat1622float2(*(__nv_bfloat162*)&u3.y);
        acc.x = fmaf(w0, a0.x, acc.x); acc.y = fmaf(w0, a0.y, acc.y);
        acc.z = fmaf(w0, b0.x, acc.z); acc.w = fmaf(w0, b0.y, acc.w);
        acc.x = fmaf(w1, a1.x, acc.x); acc.y = fmaf(w1, a1.y, acc.y);
        acc.z = fmaf(w1, b1.x, acc.z); acc.w = fmaf(w1, b1.y, acc.w);
        acc.x = fmaf(w2, a2.x, acc.x); acc.y = fmaf(w2, a2.y, acc.y);
        acc.z = fmaf(w2, b2.x, acc.z); acc.w = fmaf(w2, b2.y, acc.w);
        acc.x = fmaf(w3, a3.x, acc.x); acc.y = fmaf(w3, a3.y, acc.y);
        acc.z = fmaf(w3, b3.x, acc.z); acc.w = fmaf(w3, b3.y, acc.w);
    }
    for (; e < end; e++) {
        int2 m = g_csr[e];
        uint2 u = ((const uint2*)(X + (size_t)m.x * 128))[ln];
        float w = __int_as_float(m.y);
        float2 a = __bfloat1622float2(*(__nv_bfloat162*)&u.x);
        float2 b = __bfloat1622float2(*(__nv_bfloat162*)&u.y);
        acc.x = fmaf(w, a.x, acc.x); acc.y = fmaf(w, a.y, acc.y);
        acc.z = fmaf(w, b.x, acc.z); acc.w = fmaf(w, b.y, acc.w);
    }

    __nv_bfloat16 o0 = __float2bfloat16(acc.x), o1 = __float2bfloat16(acc.y);
    __nv_bfloat16 o2 = __float2bfloat16(acc.z), o3 = __float2bfloat16(acc.w);
    uint2 u;
    u.x = (uint32_t)__bfloat16_as_ushort(o0) | ((uint32_t)__bfloat16_as_ushort(o1) << 16);
    u.y = (uint32_t)__bfloat16_as_ushort(o2) | ((uint32_t)__bfloat16_as_ushort(o3) << 16);
    ((uint2*)(g_G + (size_t)node * 128))[ln] = u;
}

// ================= HMMA bf16 m16n8k16 =================
__device__ __forceinline__ void mma_bf16(float* c, const uint32_t* a, uint32_t b0, uint32_t b1) {
    asm volatile(
        "mma.sync.aligned.m16n8k16.row.col.f32.bf16.bf16.f32 "
        "{%0,%1,%2,%3}, {%4,%5,%6,%7}, {%8,%9}, {%0,%1,%2,%3};"
        : "+f"(c[0]), "+f"(c[1]), "+f"(c[2]), "+f"(c[3])
        : "r"(a[0]), "r"(a[1]), "r"(a[2]), "r"(a[3]), "r"(b0), "r"(b1));
}

// ====== GEMM + fused epilogue: Out = relu(G[M x 128] @ (Whi+Wlo)T + b), 2-pass compensated ======
// 256 thr = 8 warps; block tile 128 x N. W pre-interleaved: chunk[(k08*N+n)*4+q] = {b0hi,b1hi,b0lo,b1lo}.
template <int N, bool F32OUT>
__global__ __launch_bounds__(256)
void k_gemm(const __nv_bfloat16* __restrict__ G, const uint4* __restrict__ Wc,
            const float* __restrict__ bias, void* __restrict__ Out) {
    constexpr int NT = N / 8;
    constexpr int NCH = 32 * N;                // chunks: 8*N*4
    extern __shared__ uint4 sW[];

    int tid = threadIdx.x, wid = tid >> 5, lane = tid & 31;

    #pragma unroll
    for (int i = tid; i < NCH; i += 256) sW[i] = Wc[i];
    __syncthreads();

    int row0 = blockIdx.x * 128 + wid * 16;
    int grp = lane >> 2;                       // 0..7
    int q   = lane & 3;
    int qk  = q * 2;

    float acc[NT][4];
    #pragma unroll
    for (int j = 0; j < NT; j++)
        #pragma unroll
        for (int p = 0; p < 4; p++) acc[j][p] = 0.f;

    #pragma unroll
    for (int k08 = 0; k08 < 8; k08++) {
        size_t ab = (size_t)(row0 + grp) * 128 + k08 * 16 + qk;
        uint32_t a[4];
        a[0] = *(const uint32_t*)(G + ab);
        a[1] = *(const uint32_t*)(G + ab + 8 * 128);
        a[2] = *(const uint32_t*)(G + ab + 8);
        a[3] = *(const uint32_t*)(G + ab + 8 * 128 + 8);

        #pragma unroll
        for (int j = 0; j < NT; j++) {
            uint4 bb = sW[(k08 * N + j * 8 + grp) * 4 + q];   // one LDS.128
            mma_bf16(acc[j], a, bb.x, bb.y);   // A * W_hi
            mma_bf16(acc[j], a, bb.z, bb.w);   // A * W_lo
        }
    }

    int rc = row0 + grp;
    int cc = (lane & 3) * 2;
    #pragma unroll
    for (int j = 0; j < NT; j++) {
        int col = j * 8 + cc;
        float bx = bias[col], by = bias[col + 1];
        float v0 = fmaxf(acc[j][0] + bx, 0.f), v1 = fmaxf(acc[j][1] + by, 0.f);
        float v2 = fmaxf(acc[j][2] + bx, 0.f), v3 = fmaxf(acc[j][3] + by, 0.f);
        if (F32OUT) {
            float* O = (float*)Out;
            if (rc < NN)     *(float2*)&O[(size_t)rc * N + col]       = make_float2(v0, v1);
            if (rc + 8 < NN) *(float2*)&O[(size_t)(rc + 8) * N + col] = make_float2(v2, v3);
        } else {
            __nv_bfloat16* O = (__nv_bfloat16*)Out;
            if (rc < NN) {
                __nv_bfloat162 h = __floats2bfloat162_rn(v0, v1);
                *(uint32_t*)&O[(size_t)rc * N + col] = *(uint32_t*)&h;
            }
            if (rc + 8 < NN) {
                __nv_bfloat162 h = __floats2bfloat162_rn(v2, v3);
                *(uint32_t*)&O[(size_t)(rc + 8) * N + col] = *(uint32_t*)&h;
            }
        }
    }
}

// ---------------- fused mean-pool (batch is sorted) + MLP head ----------------
__device__ __forceinline__ int lower_bound_batch(const int* __restrict__ batch, int key) {
    int lo = 0, hi = NN;
    while (lo < hi) {
        int mid = (lo + hi) >> 1;
        if (batch[mid] < key) lo = mid + 1; else hi = mid;
    }
    return lo;
}

__global__ __launch_bounds__(256)
void k_pool_mlp(const float* __restrict__ A, const int* __restrict__ batch,
                const float* __restrict__ demo,
                const float* __restrict__ Wf1, const float* __restrict__ bf1,
                const float* __restrict__ Wf2, const float* __restrict__ bf2,
                const float* __restrict__ Wf3, const float* __restrict__ bf3,
                float* __restrict__ out) {
    int g = blockIdx.x;
    int t = threadIdx.x;
    __shared__ int s_beg, s_end;
    __shared__ float sp[4][64];
    __shared__ float z[72];
    __shared__ float z1[64];
    __shared__ float z2[32];

    if (t == 0) s_beg = lower_bound_batch(batch, g);
    if (t == 1) s_end = lower_bound_batch(batch, g + 1);
    __syncthreads();
    int beg = s_beg, end = s_end;

    int c = t & 63, rg = t >> 6;
    float acc = 0.f;
    for (int r = beg + rg; r < end; r += 4)
        acc += A[(size_t)r * OUTC + c];
    sp[rg][c] = acc;
    __syncthreads();

    if (t < 64) {
        float s = sp[0][t] + sp[1][t] + sp[2][t] + sp[3][t];
        float invc = 1.f / fmaxf((float)(end - beg), 1.f);
        z[t] = s * invc;
    }
    if (t < DEMO) z[64 + t] = demo[g * DEMO + t];
    __syncthreads();

    if (t < 64) {
        float a = bf1[t];
        #pragma unroll 8
        for (int k = 0; k < 72; k++) a += z[k] * Wf1[k * 64 + t];
        z1[t] = fmaxf(a, 0.f);
    }
    __syncthreads();
    if (t < 32) {
        float a = bf2[t];
        #pragma unroll 8
        for (int k = 0; k < 64; k++) a += z1[k] * Wf2[k * 32 + t];
        z2[t] = fmaxf(a, 0.f);
    }
    __syncthreads();
    if (t < 2) {
        float a = bf3[t];
        #pragma unroll
        for (int k = 0; k < 32; k++) a += z2[k] * Wf3[k * 2 + t];
        out[g * 2 + t] = a;
    }
}

// ---------------- launch ----------------
extern "C" void kernel_launch(void* const* d_in, const int* in_sizes, int n_in,
                              void* d_out, int out_size) {
    const float* x     = (const float*)d_in[0];
    const int*   ei    = (const int*)  d_in[1];   // [2, NE]
    const int*   batch = (const int*)  d_in[2];
    const float* demo  = (const float*)d_in[3];
    const float* W1 = (const float*)d_in[4];  const float* b1 = (const float*)d_in[5];
    const float* W2 = (const float*)d_in[6];  const float* b2 = (const float*)d_in[7];
    const float* W3 = (const float*)d_in[8];  const float* b3 = (const float*)d_in[9];
    const float* Wf1 = (const float*)d_in[10]; const float* bf1 = (const float*)d_in[11];
    const float* Wf2 = (const float*)d_in[12]; const float* bf2 = (const float*)d_in[13];
    const float* Wf3 = (const float*)d_in[14]; const float* bf3 = (const float*)d_in[15];
    float* out = (float*)d_out;

    const int* src = ei;
    const int* dst = ei + NE;

    float* A;
    __nv_bfloat16 *Xb, *Ab, *G;
    uint4* Wc;
    cudaGetSymbolAddress((void**)&A,  g_A);
    cudaGetSymbolAddress((void**)&Xb, g_Xb);
    cudaGetSymbolAddress((void**)&Ab, g_Ab);
    cudaGetSymbolAddress((void**)&G,  g_G);
    cudaGetSymbolAddress((void**)&Wc, g_Wint);

    const int SMEM128 = 32 * 128 * 16;   // 65536
    const int SMEM64  = 32 * 64  * 16;   // 32768
    cudaFuncSetAttribute(k_gemm<128, false>, cudaFuncAttributeMaxDynamicSharedMemorySize, SMEM128);
    cudaFuncSetAttribute(k_gemm<64,  true>,  cudaFuncAttributeMaxDynamicSharedMemorySize, SMEM64);

    const int T = 256;
    // --- fused prep (deg atomics + x->bf16 + W interleave) ---
    k_prep<<<(NN * 32 + T - 1) / T, T>>>(x, W1, W2, W3, dst);
    // --- CSR build ---
    k_scan1<<<SCAN_NBLK, SCAN_BLK>>>();
    k_scan3<<<(NN + T - 1) / T, T>>>();
    k_fill_csr<<<(NEL + T - 1) / T, T>>>(src, dst);

    const int AGG_GRID = (NN + 7) / 8;
    // --- layer 1: G = S @ Xb ; Ab = relu(G @ W1 + b1) ---
    k_agg<<<AGG_GRID, 256>>>(Xb);
    k_gemm<128, false><<<NTILES, 256, SMEM128>>>(G, Wc, b1, Ab);
    // --- layer 2 ---
    k_agg<<<AGG_GRID, 256>>>(Ab);
    k_gemm<128, false><<<NTILES, 256, SMEM128>>>(G, Wc + WC_L2, b2, Ab);
    // --- layer 3 (N=64, fp32 out) ---
    k_agg<<<AGG_GRID, 256>>>(Ab);
    k_gemm<64, true><<<NTILES, 256, SMEM64>>>(G, Wc + WC_L3, b3, A);

    // --- fused pooling + MLP head ---
    k_pool_mlp<<<NG, 256>>>(A, batch, demo, Wf1, bf1, Wf2, bf2, Wf3, bf3, out);
}